// round 3
// baseline (speedup 1.0000x reference)
#include <cuda_runtime.h>
#include <cuda_bf16.h>
#include <math.h>

// Problem dims (fixed by the reference)
constexpr int BATCH = 2;
constexpr int SEQ   = 2048;
constexpr int DIM   = 1024;
constexpr int HEADS = 8;
constexpr int HD    = 128;           // DIM / HEADS
constexpr int M_ROWS = BATCH * SEQ;  // 4096

// Scratch (static device allocations — no runtime alloc)
__device__ float g_rinv[SEQ * SEQ];          // 16 MB: 1/(dist^2 + eps)
__device__ float g_masses[BATCH * HEADS * SEQ];
__device__ float g_v[M_ROWS * DIM];          // 16 MB
__device__ float g_ho[M_ROWS * DIM];         // 16 MB

// ---------------------------------------------------------------------------
// Kernel 1: rinv[q][k] = 1 / (dist_sq + 1e-6)
// ---------------------------------------------------------------------------
__global__ __launch_bounds__(256) void dist_kernel(const float* __restrict__ pe) {
    int idx = blockIdx.x * 256 + threadIdx.x;     // exactly SEQ*SEQ threads
    int q = idx >> 11;
    int k = idx & (SEQ - 1);
    const float4* P = (const float4*)pe;          // 8 floats per position
    float4 qa = P[q * 2], qb = P[q * 2 + 1];
    float4 ka = P[k * 2], kb = P[k * 2 + 1];
    float dx0 = qa.x - ka.x, dx1 = qa.y - ka.y, dx2 = qa.z - ka.z, dx3 = qa.w - ka.w;
    float dx4 = qb.x - kb.x, dx5 = qb.y - kb.y, dx6 = qb.z - kb.z, dx7 = qb.w - kb.w;
    float ss = dx0*dx0 + dx1*dx1 + dx2*dx2 + dx3*dx3
             + dx4*dx4 + dx5*dx5 + dx6*dx6 + dx7*dx7;
    float d = sqrtf(ss + 1e-12f);
    d = d * (1.0f + 0.15f * sinf(d));
    d = fmaxf(d, 0.0f);
    g_rinv[idx] = 1.0f / (d * d + 1e-6f);
}

// ---------------------------------------------------------------------------
// Kernel 2: masses[b,h,s] = sigmoid( dot(x[b,s,h*128:...], mass_w[h]) )
// One warp per (b,s,h).
// ---------------------------------------------------------------------------
__global__ __launch_bounds__(256) void masses_kernel(const float* __restrict__ x,
                                                     const float* __restrict__ mw) {
    int warp = (blockIdx.x * 256 + threadIdx.x) >> 5;
    int lane = threadIdx.x & 31;
    int h  = warp & (HEADS - 1);
    int bs = warp >> 3;                           // b*SEQ + s
    const float4* xp = (const float4*)(x + (size_t)bs * DIM + h * HD);
    const float4* wp = (const float4*)(mw + h * HD);
    float4 xv = xp[lane];
    float4 wv = wp[lane];
    float s = xv.x*wv.x + xv.y*wv.y + xv.z*wv.z + xv.w*wv.w;
    #pragma unroll
    for (int o = 16; o; o >>= 1) s += __shfl_xor_sync(0xFFFFFFFFu, s, o);
    if (lane == 0) {
        int b = bs >> 11, ss = bs & (SEQ - 1);
        g_masses[((size_t)b * HEADS + h) * SEQ + ss] = 1.0f / (1.0f + __expf(-s));
    }
}

// ---------------------------------------------------------------------------
// Kernel 3/5: C[M][N] = A[M][K] * W[N][K]^T  (M=4096, N=K=1024)
// 128x128 tile, BK=8, 256 threads, 8x8 per thread.
// ---------------------------------------------------------------------------
__global__ __launch_bounds__(256) void sgemm_nt(const float* __restrict__ A,
                                                const float* __restrict__ W,
                                                float* __restrict__ C) {
    __shared__ float As[8][128];
    __shared__ float Bs[8][128];
    const int bn = blockIdx.x;       // N tile (8)
    const int bm = blockIdx.y;       // M tile (32)
    const int t  = threadIdx.x;
    const int ty = t >> 4, tx = t & 15;

    const int lrow = t >> 1;               // 0..127
    const int lseg = (t & 1) * 4;          // 0 or 4
    const float* Aptr = A + ((size_t)(bm * 128 + lrow)) * DIM + lseg;
    const float* Wptr = W + ((size_t)(bn * 128 + lrow)) * DIM + lseg;

    float acc[8][8];
    #pragma unroll
    for (int i = 0; i < 8; i++)
        #pragma unroll
        for (int j = 0; j < 8; j++) acc[i][j] = 0.0f;

    for (int k0 = 0; k0 < DIM; k0 += 8) {
        float4 av = *(const float4*)(Aptr + k0);
        float4 wv = *(const float4*)(Wptr + k0);
        As[lseg + 0][lrow] = av.x; As[lseg + 1][lrow] = av.y;
        As[lseg + 2][lrow] = av.z; As[lseg + 3][lrow] = av.w;
        Bs[lseg + 0][lrow] = wv.x; Bs[lseg + 1][lrow] = wv.y;
        Bs[lseg + 2][lrow] = wv.z; Bs[lseg + 3][lrow] = wv.w;
        __syncthreads();
        #pragma unroll
        for (int kk = 0; kk < 8; kk++) {
            float a[8], bb[8];
            *(float4*)&a[0]  = *(const float4*)&As[kk][ty * 8];
            *(float4*)&a[4]  = *(const float4*)&As[kk][ty * 8 + 4];
            *(float4*)&bb[0] = *(const float4*)&Bs[kk][tx * 8];
            *(float4*)&bb[4] = *(const float4*)&Bs[kk][tx * 8 + 4];
            #pragma unroll
            for (int i = 0; i < 8; i++)
                #pragma unroll
                for (int j = 0; j < 8; j++)
                    acc[i][j] = fmaf(a[i], bb[j], acc[i][j]);
        }
        __syncthreads();
    }
    #pragma unroll
    for (int i = 0; i < 8; i++) {
        size_t row = (size_t)(bm * 128 + ty * 8 + i);
        float4* dst = (float4*)(C + row * DIM + bn * 128 + tx * 8);
        dst[0] = make_float4(acc[i][0], acc[i][1], acc[i][2], acc[i][3]);
        dst[1] = make_float4(acc[i][4], acc[i][5], acc[i][6], acc[i][7]);
    }
}

// ---------------------------------------------------------------------------
// Kernel 4: fused force -> softmax -> @V, flash-style with FIXED max = 50.
// force in [0,50] always (clamped), so exp(f-50) is exact unnormalized softmax.
// Grid: x = q tiles (32), y = b*H+h (16). 256 threads.
// Tile: 64 queries x 128 hd; key chunks of 64.
// ---------------------------------------------------------------------------
constexpr int BQ = 64;
constexpr int KC = 64;
constexpr int ATTN_SMEM_FLOATS = KC * HD + BQ * KC + BQ + KC;
constexpr int ATTN_SMEM_BYTES  = ATTN_SMEM_FLOATS * 4;   // 49664

__global__ __launch_bounds__(256) void attn_kernel() {
    extern __shared__ float smem[];
    float* vs  = smem;                       // [KC][HD]
    float* ps  = vs + KC * HD;               // [BQ][KC]
    float* mqs = ps + BQ * KC;               // [BQ]
    float* mks = mqs + BQ;                   // [KC]

    const int bh = blockIdx.y;               // b*HEADS + h
    const int b  = bh >> 3;
    const int h  = bh & (HEADS - 1);
    const int q0 = blockIdx.x * BQ;
    const int t  = threadIdx.x;
    const int ty = t >> 4, tx = t & 15;      // ty: 4-row group, tx: 8-col group

    const float* mrow = g_masses + (size_t)bh * SEQ;
    if (t < BQ) mqs[t] = mrow[q0 + t];

    float acc[4][8];
    float den[4] = {0.f, 0.f, 0.f, 0.f};
    #pragma unroll
    for (int r = 0; r < 4; r++)
        #pragma unroll
        for (int c = 0; c < 8; c++) acc[r][c] = 0.0f;

    for (int kb = 0; kb < SEQ; kb += KC) {
        if (t < KC) mks[t] = mrow[kb + t];
        // load V chunk: vs[kk][c] = g_v[(b*SEQ + kb+kk)*DIM + h*HD + c]
        #pragma unroll
        for (int i = 0; i < 8; i++) {
            int e  = t + i * 256;            // float4 index, 0..2047
            int kk = e >> 5;                 // 32 float4 per row
            int c4 = e & 31;
            const float4* src =
                (const float4*)(g_v + ((size_t)(b * SEQ + kb + kk)) * DIM + h * HD) + c4;
            ((float4*)(vs + kk * HD))[c4] = *src;
        }
        __syncthreads();
        // compute p tile: ps[qi][kk] = exp(min(mq*mk*rinv,50)-50)
        #pragma unroll
        for (int i = 0; i < 16; i++) {
            int e  = t + i * 256;            // 0..4095
            int kk = e & 63;
            int qi = e >> 6;
            float r = g_rinv[(size_t)(q0 + qi) * SEQ + kb + kk];
            float f = fminf(mqs[qi] * mks[kk] * r, 50.0f);
            ps[qi * KC + kk] = __expf(f - 50.0f);
        }
        __syncthreads();
        // acc += p @ v ; den += row sums
        #pragma unroll 4
        for (int kk = 0; kk < KC; kk++) {
            float pv[4];
            #pragma unroll
            for (int r = 0; r < 4; r++) {
                pv[r] = ps[(ty * 4 + r) * KC + kk];
                den[r] += pv[r];
            }
            float4 v0 = *(const float4*)(vs + kk * HD + tx * 8);
            float4 v1 = *(const float4*)(vs + kk * HD + tx * 8 + 4);
            #pragma unroll
            for (int r = 0; r < 4; r++) {
                acc[r][0] = fmaf(pv[r], v0.x, acc[r][0]);
                acc[r][1] = fmaf(pv[r], v0.y, acc[r][1]);
                acc[r][2] = fmaf(pv[r], v0.z, acc[r][2]);
                acc[r][3] = fmaf(pv[r], v0.w, acc[r][3]);
                acc[r][4] = fmaf(pv[r], v1.x, acc[r][4]);
                acc[r][5] = fmaf(pv[r], v1.y, acc[r][5]);
                acc[r][6] = fmaf(pv[r], v1.z, acc[r][6]);
                acc[r][7] = fmaf(pv[r], v1.w, acc[r][7]);
            }
        }
        __syncthreads();
    }
    // write head_out[b, q, h*HD + c] = acc / den
    #pragma unroll
    for (int r = 0; r < 4; r++) {
        float rd = 1.0f / den[r];
        size_t row = (size_t)(b * SEQ + q0 + ty * 4 + r);
        float4* dst = (float4*)(g_ho + row * DIM + h * HD + tx * 8);
        dst[0] = make_float4(acc[r][0]*rd, acc[r][1]*rd, acc[r][2]*rd, acc[r][3]*rd);
        dst[1] = make_float4(acc[r][4]*rd, acc[r][5]*rd, acc[r][6]*rd, acc[r][7]*rd);
    }
}

// ---------------------------------------------------------------------------
extern "C" void kernel_launch(void* const* d_in, const int* in_sizes, int n_in,
                              void* d_out, int out_size) {
    const float* x      = (const float*)d_in[0];
    const float* mass_w = (const float*)d_in[1];
    const float* v_w    = (const float*)d_in[2];
    const float* out_w  = (const float*)d_in[3];
    const float* pos    = (const float*)d_in[4];
    float* out = (float*)d_out;

    float *pv = nullptr, *pho = nullptr;
    cudaGetSymbolAddress((void**)&pv,  g_v);
    cudaGetSymbolAddress((void**)&pho, g_ho);
    cudaFuncSetAttribute(attn_kernel,
                         cudaFuncAttributeMaxDynamicSharedMemorySize, ATTN_SMEM_BYTES);

    dist_kernel<<<(SEQ * SEQ) / 256, 256>>>(pos);
    masses_kernel<<<(BATCH * SEQ * HEADS * 32) / 256, 256>>>(x, mass_w);
    sgemm_nt<<<dim3(DIM / 128, M_ROWS / 128), 256>>>(x, v_w, pv);
    attn_kernel<<<dim3(SEQ / BQ, BATCH * HEADS), 256, ATTN_SMEM_BYTES>>>();
    sgemm_nt<<<dim3(DIM / 128, M_ROWS / 128), 256>>>(pho, out_w, out);
}

// round 5
// speedup vs baseline: 1.3564x; 1.3564x over previous
#include <cuda_runtime.h>
#include <cuda_bf16.h>
#include <math.h>
#include <stdint.h>

// Problem dims (fixed by the reference)
constexpr int BATCH = 2;
constexpr int SEQ   = 2048;
constexpr int DIM   = 1024;
constexpr int HEADS = 8;
constexpr int HD    = 128;           // DIM / HEADS
constexpr int M_ROWS = BATCH * SEQ;  // 4096

// Scratch (static device allocations — no runtime alloc)
__device__ float g_rinv[SEQ * SEQ];          // 16 MB
__device__ float g_masses[BATCH * HEADS * SEQ];
__device__ float g_v[M_ROWS * DIM];          // 16 MB
__device__ float g_ho[M_ROWS * DIM];         // 16 MB

__device__ __forceinline__ uint32_t f2tf32(float x) {
    uint32_t u;
    asm("cvt.rna.tf32.f32 %0, %1;" : "=r"(u) : "f"(x));
    return u;
}

// ---------------------------------------------------------------------------
// Kernel 1: rinv[q][k] = 1 / (dist_sq + 1e-6)
// ---------------------------------------------------------------------------
__global__ __launch_bounds__(256) void dist_kernel(const float* __restrict__ pe) {
    int idx = blockIdx.x * 256 + threadIdx.x;
    int q = idx >> 11;
    int k = idx & (SEQ - 1);
    const float4* P = (const float4*)pe;
    float4 qa = P[q * 2], qb = P[q * 2 + 1];
    float4 ka = P[k * 2], kb = P[k * 2 + 1];
    float dx0 = qa.x - ka.x, dx1 = qa.y - ka.y, dx2 = qa.z - ka.z, dx3 = qa.w - ka.w;
    float dx4 = qb.x - kb.x, dx5 = qb.y - kb.y, dx6 = qb.z - kb.z, dx7 = qb.w - kb.w;
    float ss = dx0*dx0 + dx1*dx1 + dx2*dx2 + dx3*dx3
             + dx4*dx4 + dx5*dx5 + dx6*dx6 + dx7*dx7;
    float d = sqrtf(ss + 1e-12f);
    d = d * (1.0f + 0.15f * sinf(d));
    d = fmaxf(d, 0.0f);
    g_rinv[idx] = 1.0f / (d * d + 1e-6f);
}

// ---------------------------------------------------------------------------
// Kernel 2: masses[b,h,s] = sigmoid(dot(x[b,s,h*128:..], mass_w[h]))
// ---------------------------------------------------------------------------
__global__ __launch_bounds__(256) void masses_kernel(const float* __restrict__ x,
                                                     const float* __restrict__ mw) {
    int warp = (blockIdx.x * 256 + threadIdx.x) >> 5;
    int lane = threadIdx.x & 31;
    int h  = warp & (HEADS - 1);
    int bs = warp >> 3;
    const float4* xp = (const float4*)(x + (size_t)bs * DIM + h * HD);
    const float4* wp = (const float4*)(mw + h * HD);
    float4 xv = xp[lane];
    float4 wv = wp[lane];
    float s = xv.x*wv.x + xv.y*wv.y + xv.z*wv.z + xv.w*wv.w;
    #pragma unroll
    for (int o = 16; o; o >>= 1) s += __shfl_xor_sync(0xFFFFFFFFu, s, o);
    if (lane == 0) {
        int b = bs >> 11, ss = bs & (SEQ - 1);
        g_masses[((size_t)b * HEADS + h) * SEQ + ss] = 1.0f / (1.0f + __expf(-s));
    }
}

// ---------------------------------------------------------------------------
// Kernels 3/5: C[M][N] = A[M][K] * W[N][K]^T via tf32 mma.sync (m16n8k8).
// Block tile 128x128, BK=16, 256 threads = 8 warps in 4(m) x 2(n),
// each warp computes 32x64. Inputs rounded to tf32 (rna) when staged.
// smem padded to 20 floats/row -> fragment loads are bank-conflict-free.
// ---------------------------------------------------------------------------
constexpr int GBK = 16;
__global__ __launch_bounds__(256) void gemm_tf32(const float* __restrict__ A,
                                                 const float* __restrict__ W,
                                                 float* __restrict__ C) {
    __shared__ uint32_t As[128][GBK + 4];   // [m][k]
    __shared__ uint32_t Ws[128][GBK + 4];   // [n][k]
    const int t    = threadIdx.x;
    const int warp = t >> 5, lane = t & 31;
    const int wm = warp >> 1, wn = warp & 1;     // 4x2 warp grid
    const int g  = lane >> 2, tig = lane & 3;    // groupID, thread-in-group
    const int bm = blockIdx.y * 128, bn = blockIdx.x * 128;

    float acc[2][8][4];
    #pragma unroll
    for (int mt = 0; mt < 2; mt++)
        #pragma unroll
        for (int nt = 0; nt < 8; nt++)
            #pragma unroll
            for (int c = 0; c < 4; c++) acc[mt][nt][c] = 0.0f;

    for (int k0 = 0; k0 < DIM; k0 += GBK) {
        #pragma unroll
        for (int i = 0; i < 2; i++) {
            int idx = t + i * 256;           // 0..511
            int row = idx >> 2, seg = (idx & 3) * 4;
            float4 a = *(const float4*)(A + (size_t)(bm + row) * DIM + k0 + seg);
            float4 w = *(const float4*)(W + (size_t)(bn + row) * DIM + k0 + seg);
            As[row][seg + 0] = f2tf32(a.x); As[row][seg + 1] = f2tf32(a.y);
            As[row][seg + 2] = f2tf32(a.z); As[row][seg + 3] = f2tf32(a.w);
            Ws[row][seg + 0] = f2tf32(w.x); Ws[row][seg + 1] = f2tf32(w.y);
            Ws[row][seg + 2] = f2tf32(w.z); Ws[row][seg + 3] = f2tf32(w.w);
        }
        __syncthreads();
        #pragma unroll
        for (int kk = 0; kk < GBK; kk += 8) {
            uint32_t af[2][4];
            #pragma unroll
            for (int mt = 0; mt < 2; mt++) {
                int r = wm * 32 + mt * 16;
                af[mt][0] = As[r + g][kk + tig];
                af[mt][1] = As[r + g + 8][kk + tig];
                af[mt][2] = As[r + g][kk + tig + 4];
                af[mt][3] = As[r + g + 8][kk + tig + 4];
            }
            uint32_t bf[8][2];
            #pragma unroll
            for (int nt = 0; nt < 8; nt++) {
                int c = wn * 64 + nt * 8;
                bf[nt][0] = Ws[c + g][kk + tig];
                bf[nt][1] = Ws[c + g][kk + tig + 4];
            }
            #pragma unroll
            for (int mt = 0; mt < 2; mt++)
                #pragma unroll
                for (int nt = 0; nt < 8; nt++) {
                    asm volatile(
                        "mma.sync.aligned.m16n8k8.row.col.f32.tf32.tf32.f32 "
                        "{%0,%1,%2,%3}, {%4,%5,%6,%7}, {%8,%9}, {%0,%1,%2,%3};"
                        : "+f"(acc[mt][nt][0]), "+f"(acc[mt][nt][1]),
                          "+f"(acc[mt][nt][2]), "+f"(acc[mt][nt][3])
                        : "r"(af[mt][0]), "r"(af[mt][1]), "r"(af[mt][2]), "r"(af[mt][3]),
                          "r"(bf[nt][0]), "r"(bf[nt][1]));
                }
        }
        __syncthreads();
    }
    // store: c0,c1 -> row g, cols 2*tig,2*tig+1 ; c2,c3 -> row g+8
    #pragma unroll
    for (int mt = 0; mt < 2; mt++) {
        #pragma unroll
        for (int nt = 0; nt < 8; nt++) {
            size_t r0 = (size_t)(bm + wm * 32 + mt * 16 + g);
            int col = bn + wn * 64 + nt * 8 + 2 * tig;
            *(float2*)(C + r0 * DIM + col) =
                make_float2(acc[mt][nt][0], acc[mt][nt][1]);
            *(float2*)(C + (r0 + 8) * DIM + col) =
                make_float2(acc[mt][nt][2], acc[mt][nt][3]);
        }
    }
}

// ---------------------------------------------------------------------------
// Kernel 4: fused force -> softmax -> @V with FIXED softmax max = 50.
// Vectorized: rinv loads, ps stores and ps reads all 128-bit.
// ---------------------------------------------------------------------------
constexpr int BQ = 64;
constexpr int KC = 64;
constexpr int ATTN_SMEM_FLOATS = KC * HD + BQ * KC + BQ + KC;
constexpr int ATTN_SMEM_BYTES  = ATTN_SMEM_FLOATS * 4;   // 49664

__global__ __launch_bounds__(256) void attn_kernel() {
    extern __shared__ float smem[];
    float* vs  = smem;                       // [KC][HD]
    float* ps  = vs + KC * HD;               // [BQ][KC]
    float* mqs = ps + BQ * KC;               // [BQ]
    float* mks = mqs + BQ;                   // [KC]

    const int bh = blockIdx.y;
    const int b  = bh >> 3;
    const int h  = bh & (HEADS - 1);
    const int q0 = blockIdx.x * BQ;
    const int t  = threadIdx.x;
    const int ty = t >> 4, tx = t & 15;

    const float* mrow = g_masses + (size_t)bh * SEQ;
    if (t < BQ) mqs[t] = mrow[q0 + t];

    float acc[4][8];
    float den[4] = {0.f, 0.f, 0.f, 0.f};
    #pragma unroll
    for (int r = 0; r < 4; r++)
        #pragma unroll
        for (int c = 0; c < 8; c++) acc[r][c] = 0.0f;

    for (int kb = 0; kb < SEQ; kb += KC) {
        if (t < KC) mks[t] = mrow[kb + t];
        // load V chunk (float4): vs[kk][c] = g_v[(b*SEQ+kb+kk)*DIM + h*HD + c]
        #pragma unroll
        for (int i = 0; i < 8; i++) {
            int e  = t + i * 256;            // 0..2047
            int kk = e >> 5;
            int c4 = e & 31;
            const float4* src =
                (const float4*)(g_v + ((size_t)(b * SEQ + kb + kk)) * DIM + h * HD) + c4;
            ((float4*)(vs + kk * HD))[c4] = *src;
        }
        __syncthreads();
        // p tile, vectorized: each thread handles 4 float4 groups
        #pragma unroll
        for (int i = 0; i < 4; i++) {
            int e  = t + i * 256;            // 0..1023 (float4 groups)
            int qi = e >> 4;                 // 16 groups per q row
            int k4 = (e & 15) * 4;
            float4 rv = *(const float4*)(g_rinv + (size_t)(q0 + qi) * SEQ + kb + k4);
            float mq = mqs[qi];
            float4 ev;
            ev.x = __expf(fminf(mq * mks[k4 + 0] * rv.x, 50.0f) - 50.0f);
            ev.y = __expf(fminf(mq * mks[k4 + 1] * rv.y, 50.0f) - 50.0f);
            ev.z = __expf(fminf(mq * mks[k4 + 2] * rv.z, 50.0f) - 50.0f);
            ev.w = __expf(fminf(mq * mks[k4 + 3] * rv.w, 50.0f) - 50.0f);
            *(float4*)(ps + qi * KC + k4) = ev;
        }
        __syncthreads();
        // acc += p @ v, p read as float4 over kk
        #pragma unroll 4
        for (int kk = 0; kk < KC; kk += 4) {
            float4 p[4];
            #pragma unroll
            for (int r = 0; r < 4; r++) {
                p[r] = *(const float4*)(ps + (ty * 4 + r) * KC + kk);
                den[r] += p[r].x + p[r].y + p[r].z + p[r].w;
            }
            #pragma unroll
            for (int j = 0; j < 4; j++) {
                float4 v0 = *(const float4*)(vs + (kk + j) * HD + tx * 8);
                float4 v1 = *(const float4*)(vs + (kk + j) * HD + tx * 8 + 4);
                #pragma unroll
                for (int r = 0; r < 4; r++) {
                    float pv = j == 0 ? p[r].x : j == 1 ? p[r].y : j == 2 ? p[r].z : p[r].w;
                    acc[r][0] = fmaf(pv, v0.x, acc[r][0]);
                    acc[r][1] = fmaf(pv, v0.y, acc[r][1]);
                    acc[r][2] = fmaf(pv, v0.z, acc[r][2]);
                    acc[r][3] = fmaf(pv, v0.w, acc[r][3]);
                    acc[r][4] = fmaf(pv, v1.x, acc[r][4]);
                    acc[r][5] = fmaf(pv, v1.y, acc[r][5]);
                    acc[r][6] = fmaf(pv, v1.z, acc[r][6]);
                    acc[r][7] = fmaf(pv, v1.w, acc[r][7]);
                }
            }
        }
        __syncthreads();
    }
    #pragma unroll
    for (int r = 0; r < 4; r++) {
        float rd = 1.0f / den[r];
        size_t row = (size_t)(b * SEQ + q0 + ty * 4 + r);
        float4* dst = (float4*)(g_ho + row * DIM + h * HD + tx * 8);
        dst[0] = make_float4(acc[r][0]*rd, acc[r][1]*rd, acc[r][2]*rd, acc[r][3]*rd);
        dst[1] = make_float4(acc[r][4]*rd, acc[r][5]*rd, acc[r][6]*rd, acc[r][7]*rd);
    }
}

// ---------------------------------------------------------------------------
extern "C" void kernel_launch(void* const* d_in, const int* in_sizes, int n_in,
                              void* d_out, int out_size) {
    const float* x      = (const float*)d_in[0];
    const float* mass_w = (const float*)d_in[1];
    const float* v_w    = (const float*)d_in[2];
    const float* out_w  = (const float*)d_in[3];
    const float* pos    = (const float*)d_in[4];
    float* out = (float*)d_out;

    float *pv = nullptr, *pho = nullptr;
    cudaGetSymbolAddress((void**)&pv,  g_v);
    cudaGetSymbolAddress((void**)&pho, g_ho);
    cudaFuncSetAttribute(attn_kernel,
                         cudaFuncAttributeMaxDynamicSharedMemorySize, ATTN_SMEM_BYTES);

    dist_kernel<<<(SEQ * SEQ) / 256, 256>>>(pos);
    masses_kernel<<<(BATCH * SEQ * HEADS * 32) / 256, 256>>>(x, mass_w);
    gemm_tf32<<<dim3(DIM / 128, M_ROWS / 128), 256>>>(x, v_w, pv);
    attn_kernel<<<dim3(SEQ / BQ, BATCH * HEADS), 256, ATTN_SMEM_BYTES>>>();
    gemm_tf32<<<dim3(DIM / 128, M_ROWS / 128), 256>>>(pho, out_w, out);
}

// round 7
// speedup vs baseline: 2.8085x; 2.0706x over previous
#include <cuda_runtime.h>
#include <cuda_bf16.h>
#include <math.h>
#include <stdint.h>

constexpr int BATCH = 2;
constexpr int SEQ   = 2048;
constexpr int DIM   = 1024;
constexpr int HEADS = 8;
constexpr int HD    = 128;
constexpr int M_ROWS = BATCH * SEQ;  // 4096

__device__ float g_rinv[SEQ * SEQ];
__device__ float g_masses[BATCH * HEADS * SEQ];
__device__ float g_v[M_ROWS * DIM];
__device__ float g_ho[M_ROWS * DIM];

__device__ __forceinline__ uint32_t f2tf32(float x) {
    uint32_t u;
    asm("cvt.rna.tf32.f32 %0, %1;" : "=r"(u) : "f"(x));
    return u;
}

// ---------------------------------------------------------------------------
// Kernel 1: rinv[q][k] = 1 / (dist_sq + 1e-6)
// ---------------------------------------------------------------------------
__global__ __launch_bounds__(256) void dist_kernel(const float* __restrict__ pe) {
    int idx = blockIdx.x * 256 + threadIdx.x;
    int q = idx >> 11;
    int k = idx & (SEQ - 1);
    const float4* P = (const float4*)pe;
    float4 qa = P[q * 2], qb = P[q * 2 + 1];
    float4 ka = P[k * 2], kb = P[k * 2 + 1];
    float dx0 = qa.x - ka.x, dx1 = qa.y - ka.y, dx2 = qa.z - ka.z, dx3 = qa.w - ka.w;
    float dx4 = qb.x - kb.x, dx5 = qb.y - kb.y, dx6 = qb.z - kb.z, dx7 = qb.w - kb.w;
    float ss = dx0*dx0 + dx1*dx1 + dx2*dx2 + dx3*dx3
             + dx4*dx4 + dx5*dx5 + dx6*dx6 + dx7*dx7;
    float d = sqrtf(ss + 1e-12f);
    d = d * (1.0f + 0.15f * sinf(d));
    d = fmaxf(d, 0.0f);
    g_rinv[idx] = 1.0f / (d * d + 1e-6f);
}

// ---------------------------------------------------------------------------
// Kernel 2: masses
// ---------------------------------------------------------------------------
__global__ __launch_bounds__(256) void masses_kernel(const float* __restrict__ x,
                                                     const float* __restrict__ mw) {
    int warp = (blockIdx.x * 256 + threadIdx.x) >> 5;
    int lane = threadIdx.x & 31;
    int h  = warp & (HEADS - 1);
    int bs = warp >> 3;
    const float4* xp = (const float4*)(x + (size_t)bs * DIM + h * HD);
    const float4* wp = (const float4*)(mw + h * HD);
    float4 xv = xp[lane];
    float4 wv = wp[lane];
    float s = xv.x*wv.x + xv.y*wv.y + xv.z*wv.z + xv.w*wv.w;
    #pragma unroll
    for (int o = 16; o; o >>= 1) s += __shfl_xor_sync(0xFFFFFFFFu, s, o);
    if (lane == 0) {
        int b = bs >> 11, ss = bs & (SEQ - 1);
        g_masses[((size_t)b * HEADS + h) * SEQ + ss] = 1.0f / (1.0f + __expf(-s));
    }
}

// ---------------------------------------------------------------------------
// Kernels 3/5: tf32 tensor-core GEMM, C = A * W^T (128x128 tile, BK=16)
// ---------------------------------------------------------------------------
constexpr int GBK = 16;
__global__ __launch_bounds__(256) void gemm_tf32(const float* __restrict__ A,
                                                 const float* __restrict__ W,
                                                 float* __restrict__ C) {
    __shared__ uint32_t As[128][GBK + 4];
    __shared__ uint32_t Ws[128][GBK + 4];
    const int t    = threadIdx.x;
    const int warp = t >> 5, lane = t & 31;
    const int wm = warp >> 1, wn = warp & 1;
    const int g  = lane >> 2, tig = lane & 3;
    const int bm = blockIdx.y * 128, bn = blockIdx.x * 128;

    float acc[2][8][4];
    #pragma unroll
    for (int mt = 0; mt < 2; mt++)
        #pragma unroll
        for (int nt = 0; nt < 8; nt++)
            #pragma unroll
            for (int c = 0; c < 4; c++) acc[mt][nt][c] = 0.0f;

    for (int k0 = 0; k0 < DIM; k0 += GBK) {
        #pragma unroll
        for (int i = 0; i < 2; i++) {
            int idx = t + i * 256;
            int row = idx >> 2, seg = (idx & 3) * 4;
            float4 a = *(const float4*)(A + (size_t)(bm + row) * DIM + k0 + seg);
            float4 w = *(const float4*)(W + (size_t)(bn + row) * DIM + k0 + seg);
            As[row][seg + 0] = f2tf32(a.x); As[row][seg + 1] = f2tf32(a.y);
            As[row][seg + 2] = f2tf32(a.z); As[row][seg + 3] = f2tf32(a.w);
            Ws[row][seg + 0] = f2tf32(w.x); Ws[row][seg + 1] = f2tf32(w.y);
            Ws[row][seg + 2] = f2tf32(w.z); Ws[row][seg + 3] = f2tf32(w.w);
        }
        __syncthreads();
        #pragma unroll
        for (int kk = 0; kk < GBK; kk += 8) {
            uint32_t af[2][4];
            #pragma unroll
            for (int mt = 0; mt < 2; mt++) {
                int r = wm * 32 + mt * 16;
                af[mt][0] = As[r + g][kk + tig];
                af[mt][1] = As[r + g + 8][kk + tig];
                af[mt][2] = As[r + g][kk + tig + 4];
                af[mt][3] = As[r + g + 8][kk + tig + 4];
            }
            uint32_t bf[8][2];
            #pragma unroll
            for (int nt = 0; nt < 8; nt++) {
                int c = wn * 64 + nt * 8;
                bf[nt][0] = Ws[c + g][kk + tig];
                bf[nt][1] = Ws[c + g][kk + tig + 4];
            }
            #pragma unroll
            for (int mt = 0; mt < 2; mt++)
                #pragma unroll
                for (int nt = 0; nt < 8; nt++) {
                    asm volatile(
                        "mma.sync.aligned.m16n8k8.row.col.f32.tf32.tf32.f32 "
                        "{%0,%1,%2,%3}, {%4,%5,%6,%7}, {%8,%9}, {%0,%1,%2,%3};"
                        : "+f"(acc[mt][nt][0]), "+f"(acc[mt][nt][1]),
                          "+f"(acc[mt][nt][2]), "+f"(acc[mt][nt][3])
                        : "r"(af[mt][0]), "r"(af[mt][1]), "r"(af[mt][2]), "r"(af[mt][3]),
                          "r"(bf[nt][0]), "r"(bf[nt][1]));
                }
        }
        __syncthreads();
    }
    #pragma unroll
    for (int mt = 0; mt < 2; mt++) {
        #pragma unroll
        for (int nt = 0; nt < 8; nt++) {
            size_t r0 = (size_t)(bm + wm * 32 + mt * 16 + g);
            int col = bn + wn * 64 + nt * 8 + 2 * tig;
            *(float2*)(C + r0 * DIM + col) =
                make_float2(acc[mt][nt][0], acc[mt][nt][1]);
            *(float2*)(C + (r0 + 8) * DIM + col) =
                make_float2(acc[mt][nt][2], acc[mt][nt][3]);
        }
    }
}

// ---------------------------------------------------------------------------
// Kernel 4: fused force->softmax->@V, PV on tf32 tensor cores.
// Block: 64 q-rows x 128 hd cols, key chunks of 64. 8 warps (2m x 4n),
// each warp 32x32 output. Fixed softmax max = 50 (force clamped to [0,50]).
// den computed in fp32 from unrounded p (shfl-reduce), never through smem mma.
// smem: vsr[64][136] tf32 V chunk (stride%32==8 -> B-frag conflict-free),
//       ps[64][68] tf32 P (stride%32==4 -> A-frag conflict-free).
// ---------------------------------------------------------------------------
constexpr int KC = 64;
constexpr int VSTR = 136;
constexpr int PSTR = 68;
constexpr int ATTN_SMEM_FLOATS = KC * VSTR + 64 * PSTR + 64;
constexpr int ATTN_SMEM_BYTES  = ATTN_SMEM_FLOATS * 4;   // 52736

__global__ __launch_bounds__(256) void attn_kernel() {
    extern __shared__ float smem[];
    float*    vsr   = smem;                    // [KC][VSTR] tf32 bits
    float*    ps    = vsr + KC * VSTR;         // [64][PSTR] tf32 bits
    float*    den_s = ps + 64 * PSTR;          // [64]

    const int bh = blockIdx.y;
    const int b  = bh >> 3;
    const int h  = bh & (HEADS - 1);
    const int q0 = blockIdx.x * 64;
    const int t  = threadIdx.x;
    const int warp = t >> 5, lane = t & 31;
    const int g = lane >> 2, tig = lane & 3;
    const int wm = warp >> 2, wn = warp & 3;   // 2 x 4 warp grid
    const int qi_p = t >> 2, part = t & 3;     // p-pass mapping
    const int k0p  = part * 16;

    const float* mrow = g_masses + (size_t)bh * SEQ;
    const float  mq   = mrow[q0 + qi_p];
    float denr = 0.0f;

    float acc[2][4][4];
    #pragma unroll
    for (int mt = 0; mt < 2; mt++)
        #pragma unroll
        for (int nt = 0; nt < 4; nt++)
            #pragma unroll
            for (int c = 0; c < 4; c++) acc[mt][nt][c] = 0.0f;

    for (int kb = 0; kb < SEQ; kb += KC) {
        // --- stage V chunk (tf32, non-transposed, stride VSTR) ---
        #pragma unroll
        for (int i = 0; i < 8; i++) {
            int e  = t + i * 256;              // 0..2047 float4 groups
            int kk = e >> 5;
            int c4 = e & 31;
            float4 v = *(const float4*)(g_v +
                         ((size_t)(b * SEQ + kb + kk)) * DIM + h * HD + c4 * 4);
            uint4 u = make_uint4(f2tf32(v.x), f2tf32(v.y), f2tf32(v.z), f2tf32(v.w));
            *(uint4*)(vsr + kk * VSTR + c4 * 4) = u;
        }
        // --- p-pass: thread owns (qi_p, k0p..k0p+15) ---
        {
            const float* rp = g_rinv + (size_t)(q0 + qi_p) * SEQ + kb + k0p;
            const float* mk = mrow + kb + k0p;
            float psum = 0.0f;
            #pragma unroll
            for (int j4 = 0; j4 < 4; j4++) {
                float4 rv = *(const float4*)(rp + j4 * 4);
                float4 mv = *(const float4*)(mk + j4 * 4);
                float e0 = __expf(fminf(mq * mv.x * rv.x, 50.0f) - 50.0f);
                float e1 = __expf(fminf(mq * mv.y * rv.y, 50.0f) - 50.0f);
                float e2 = __expf(fminf(mq * mv.z * rv.z, 50.0f) - 50.0f);
                float e3 = __expf(fminf(mq * mv.w * rv.w, 50.0f) - 50.0f);
                psum += (e0 + e1) + (e2 + e3);
                uint4 u = make_uint4(f2tf32(e0), f2tf32(e1), f2tf32(e2), f2tf32(e3));
                *(uint4*)(ps + qi_p * PSTR + k0p + j4 * 4) = u;
            }
            // reduce across the 4 lanes of this q-row (lanes qi*4+part)
            psum += __shfl_xor_sync(0xFFFFFFFFu, psum, 1);
            psum += __shfl_xor_sync(0xFFFFFFFFu, psum, 2);
            if (part == 0) denr += psum;
        }
        __syncthreads();
        // --- PV mma: 8 k-steps, 2x4 tiles per warp ---
        #pragma unroll
        for (int ks = 0; ks < 8; ks++) {
            int kk = ks * 8;
            uint32_t af[2][4];
            #pragma unroll
            for (int mt = 0; mt < 2; mt++) {
                int r = wm * 32 + mt * 16;
                const uint32_t* prow  = (const uint32_t*)(ps + (r + g) * PSTR + kk);
                const uint32_t* prow8 = (const uint32_t*)(ps + (r + g + 8) * PSTR + kk);
                af[mt][0] = prow[tig];
                af[mt][1] = prow8[tig];
                af[mt][2] = prow[tig + 4];
                af[mt][3] = prow8[tig + 4];
            }
            uint32_t bf[4][2];
            #pragma unroll
            for (int nt = 0; nt < 4; nt++) {
                int c = wn * 32 + nt * 8;
                bf[nt][0] = ((const uint32_t*)vsr)[(kk + tig) * VSTR + c + g];
                bf[nt][1] = ((const uint32_t*)vsr)[(kk + tig + 4) * VSTR + c + g];
            }
            #pragma unroll
            for (int mt = 0; mt < 2; mt++)
                #pragma unroll
                for (int nt = 0; nt < 4; nt++) {
                    asm volatile(
                        "mma.sync.aligned.m16n8k8.row.col.f32.tf32.tf32.f32 "
                        "{%0,%1,%2,%3}, {%4,%5,%6,%7}, {%8,%9}, {%0,%1,%2,%3};"
                        : "+f"(acc[mt][nt][0]), "+f"(acc[mt][nt][1]),
                          "+f"(acc[mt][nt][2]), "+f"(acc[mt][nt][3])
                        : "r"(af[mt][0]), "r"(af[mt][1]), "r"(af[mt][2]), "r"(af[mt][3]),
                          "r"(bf[nt][0]), "r"(bf[nt][1]));
                }
        }
        __syncthreads();
    }
    // publish denominators, then normalize + store
    if (part == 0) den_s[qi_p] = denr;
    __syncthreads();
    #pragma unroll
    for (int mt = 0; mt < 2; mt++) {
        int r = wm * 32 + mt * 16 + g;
        float rd0 = 1.0f / den_s[r];
        float rd8 = 1.0f / den_s[r + 8];
        #pragma unroll
        for (int nt = 0; nt < 4; nt++) {
            int col = h * HD + wn * 32 + nt * 8 + 2 * tig;
            size_t row = (size_t)(b * SEQ + q0 + r);
            *(float2*)(g_ho + row * DIM + col) =
                make_float2(acc[mt][nt][0] * rd0, acc[mt][nt][1] * rd0);
            *(float2*)(g_ho + (row + 8) * DIM + col) =
                make_float2(acc[mt][nt][2] * rd8, acc[mt][nt][3] * rd8);
        }
    }
}

// ---------------------------------------------------------------------------
extern "C" void kernel_launch(void* const* d_in, const int* in_sizes, int n_in,
                              void* d_out, int out_size) {
    const float* x      = (const float*)d_in[0];
    const float* mass_w = (const float*)d_in[1];
    const float* v_w    = (const float*)d_in[2];
    const float* out_w  = (const float*)d_in[3];
    const float* pos    = (const float*)d_in[4];
    float* out = (float*)d_out;

    float *pv = nullptr, *pho = nullptr;
    cudaGetSymbolAddress((void**)&pv,  g_v);
    cudaGetSymbolAddress((void**)&pho, g_ho);
    cudaFuncSetAttribute(attn_kernel,
                         cudaFuncAttributeMaxDynamicSharedMemorySize, ATTN_SMEM_BYTES);

    dist_kernel<<<(SEQ * SEQ) / 256, 256>>>(pos);
    masses_kernel<<<(BATCH * SEQ * HEADS * 32) / 256, 256>>>(x, mass_w);
    gemm_tf32<<<dim3(DIM / 128, M_ROWS / 128), 256>>>(x, v_w, pv);
    attn_kernel<<<dim3(SEQ / 64, BATCH * HEADS), 256, ATTN_SMEM_BYTES>>>();
    gemm_tf32<<<dim3(DIM / 128, M_ROWS / 128), 256>>>(pho, out_w, out);
}

// round 8
// speedup vs baseline: 2.8507x; 1.0150x over previous
#include <cuda_runtime.h>
#include <cuda_bf16.h>
#include <math.h>
#include <stdint.h>

constexpr int BATCH = 2;
constexpr int SEQ   = 2048;
constexpr int DIM   = 1024;
constexpr int HEADS = 8;
constexpr int HD    = 128;
constexpr int M_ROWS = BATCH * SEQ;  // 4096

__device__ float g_rinv[SEQ * SEQ];
__device__ float g_masses[BATCH * HEADS * SEQ];
__device__ float g_v[M_ROWS * DIM];
__device__ float g_ho[M_ROWS * DIM];

__device__ __forceinline__ uint32_t f2tf32(float x) {
    uint32_t u;
    asm("cvt.rna.tf32.f32 %0, %1;" : "=r"(u) : "f"(x));
    return u;
}

// ---------------------------------------------------------------------------
// Kernel 1: rinv[q][k] = 1 / (dist_sq + 1e-6)
// ---------------------------------------------------------------------------
__global__ __launch_bounds__(256) void dist_kernel(const float* __restrict__ pe) {
    int idx = blockIdx.x * 256 + threadIdx.x;
    int q = idx >> 11;
    int k = idx & (SEQ - 1);
    const float4* P = (const float4*)pe;
    float4 qa = P[q * 2], qb = P[q * 2 + 1];
    float4 ka = P[k * 2], kb = P[k * 2 + 1];
    float dx0 = qa.x - ka.x, dx1 = qa.y - ka.y, dx2 = qa.z - ka.z, dx3 = qa.w - ka.w;
    float dx4 = qb.x - kb.x, dx5 = qb.y - kb.y, dx6 = qb.z - kb.z, dx7 = qb.w - kb.w;
    float ss = dx0*dx0 + dx1*dx1 + dx2*dx2 + dx3*dx3
             + dx4*dx4 + dx5*dx5 + dx6*dx6 + dx7*dx7;
    float d = sqrtf(ss + 1e-12f);
    d = d * (1.0f + 0.15f * sinf(d));
    d = fmaxf(d, 0.0f);
    g_rinv[idx] = 1.0f / (d * d + 1e-6f);
}

// ---------------------------------------------------------------------------
// Kernel 2: masses
// ---------------------------------------------------------------------------
__global__ __launch_bounds__(256) void masses_kernel(const float* __restrict__ x,
                                                     const float* __restrict__ mw) {
    int warp = (blockIdx.x * 256 + threadIdx.x) >> 5;
    int lane = threadIdx.x & 31;
    int h  = warp & (HEADS - 1);
    int bs = warp >> 3;
    const float4* xp = (const float4*)(x + (size_t)bs * DIM + h * HD);
    const float4* wp = (const float4*)(mw + h * HD);
    float4 xv = xp[lane];
    float4 wv = wp[lane];
    float s = xv.x*wv.x + xv.y*wv.y + xv.z*wv.z + xv.w*wv.w;
    #pragma unroll
    for (int o = 16; o; o >>= 1) s += __shfl_xor_sync(0xFFFFFFFFu, s, o);
    if (lane == 0) {
        int b = bs >> 11, ss = bs & (SEQ - 1);
        g_masses[((size_t)b * HEADS + h) * SEQ + ss] = 1.0f / (1.0f + __expf(-s));
    }
}

// ---------------------------------------------------------------------------
// Kernels 3/5: tf32 tensor-core GEMM, C = A * W^T, double-buffered smem.
// 128x128 tile, BK=16, 8 warps (4m x 2n), one barrier per k-step.
// ---------------------------------------------------------------------------
constexpr int GBK = 16;

__device__ __forceinline__ void gemm_fill(uint32_t (*Asb)[GBK + 4],
                                          uint32_t (*Wsb)[GBK + 4],
                                          const float* __restrict__ A,
                                          const float* __restrict__ W,
                                          int bm, int bn, int k0, int t) {
    #pragma unroll
    for (int i = 0; i < 2; i++) {
        int idx = t + i * 256;
        int row = idx >> 2, seg = (idx & 3) * 4;
        float4 a = *(const float4*)(A + (size_t)(bm + row) * DIM + k0 + seg);
        float4 w = *(const float4*)(W + (size_t)(bn + row) * DIM + k0 + seg);
        Asb[row][seg + 0] = f2tf32(a.x); Asb[row][seg + 1] = f2tf32(a.y);
        Asb[row][seg + 2] = f2tf32(a.z); Asb[row][seg + 3] = f2tf32(a.w);
        Wsb[row][seg + 0] = f2tf32(w.x); Wsb[row][seg + 1] = f2tf32(w.y);
        Wsb[row][seg + 2] = f2tf32(w.z); Wsb[row][seg + 3] = f2tf32(w.w);
    }
}

__global__ __launch_bounds__(256) void gemm_tf32(const float* __restrict__ A,
                                                 const float* __restrict__ W,
                                                 float* __restrict__ C) {
    __shared__ uint32_t As[2][128][GBK + 4];
    __shared__ uint32_t Ws[2][128][GBK + 4];
    const int t    = threadIdx.x;
    const int warp = t >> 5, lane = t & 31;
    const int wm = warp >> 1, wn = warp & 1;
    const int g  = lane >> 2, tig = lane & 3;
    const int bm = blockIdx.y * 128, bn = blockIdx.x * 128;

    float acc[2][8][4];
    #pragma unroll
    for (int mt = 0; mt < 2; mt++)
        #pragma unroll
        for (int nt = 0; nt < 8; nt++)
            #pragma unroll
            for (int c = 0; c < 4; c++) acc[mt][nt][c] = 0.0f;

    gemm_fill(As[0], Ws[0], A, W, bm, bn, 0, t);

    constexpr int NIT = DIM / GBK;   // 64
    for (int i = 0; i < NIT; i++) {
        __syncthreads();
        if (i + 1 < NIT)
            gemm_fill(As[(i + 1) & 1], Ws[(i + 1) & 1], A, W, bm, bn, (i + 1) * GBK, t);
        uint32_t (*Ab)[GBK + 4] = As[i & 1];
        uint32_t (*Wb)[GBK + 4] = Ws[i & 1];
        #pragma unroll
        for (int kk = 0; kk < GBK; kk += 8) {
            uint32_t af[2][4];
            #pragma unroll
            for (int mt = 0; mt < 2; mt++) {
                int r = wm * 32 + mt * 16;
                af[mt][0] = Ab[r + g][kk + tig];
                af[mt][1] = Ab[r + g + 8][kk + tig];
                af[mt][2] = Ab[r + g][kk + tig + 4];
                af[mt][3] = Ab[r + g + 8][kk + tig + 4];
            }
            uint32_t bf[8][2];
            #pragma unroll
            for (int nt = 0; nt < 8; nt++) {
                int c = wn * 64 + nt * 8;
                bf[nt][0] = Wb[c + g][kk + tig];
                bf[nt][1] = Wb[c + g][kk + tig + 4];
            }
            #pragma unroll
            for (int mt = 0; mt < 2; mt++)
                #pragma unroll
                for (int nt = 0; nt < 8; nt++) {
                    asm volatile(
                        "mma.sync.aligned.m16n8k8.row.col.f32.tf32.tf32.f32 "
                        "{%0,%1,%2,%3}, {%4,%5,%6,%7}, {%8,%9}, {%0,%1,%2,%3};"
                        : "+f"(acc[mt][nt][0]), "+f"(acc[mt][nt][1]),
                          "+f"(acc[mt][nt][2]), "+f"(acc[mt][nt][3])
                        : "r"(af[mt][0]), "r"(af[mt][1]), "r"(af[mt][2]), "r"(af[mt][3]),
                          "r"(bf[nt][0]), "r"(bf[nt][1]));
                }
        }
    }
    #pragma unroll
    for (int mt = 0; mt < 2; mt++) {
        #pragma unroll
        for (int nt = 0; nt < 8; nt++) {
            size_t r0 = (size_t)(bm + wm * 32 + mt * 16 + g);
            int col = bn + wn * 64 + nt * 8 + 2 * tig;
            *(float2*)(C + r0 * DIM + col) =
                make_float2(acc[mt][nt][0], acc[mt][nt][1]);
            *(float2*)(C + (r0 + 8) * DIM + col) =
                make_float2(acc[mt][nt][2], acc[mt][nt][3]);
        }
    }
}

// ---------------------------------------------------------------------------
// Kernel 4: fused force->softmax->@V, PV on tf32 tensor cores,
// double-buffered (V,P) staging, one barrier per key chunk.
// ---------------------------------------------------------------------------
constexpr int KC = 64;
constexpr int VSTR = 136;
constexpr int PSTR = 68;
constexpr int BUFSZ = KC * VSTR + 64 * PSTR;          // floats per buffer
constexpr int ATTN_SMEM_FLOATS = 2 * BUFSZ + 64;
constexpr int ATTN_SMEM_BYTES  = ATTN_SMEM_FLOATS * 4; // 104704

__device__ __forceinline__ void attn_fill(float* __restrict__ vsr,
                                          float* __restrict__ ps,
                                          int b, int h, int kb, int t,
                                          const float* __restrict__ mrow,
                                          int q0, int qi_p, int k0p,
                                          float mq, float& denr, int part) {
    // V staging (tf32 bits, stride VSTR)
    #pragma unroll
    for (int i = 0; i < 8; i++) {
        int e  = t + i * 256;
        int kk = e >> 5;
        int c4 = e & 31;
        float4 v = *(const float4*)(g_v +
                     ((size_t)(b * SEQ + kb + kk)) * DIM + h * HD + c4 * 4);
        uint4 u = make_uint4(f2tf32(v.x), f2tf32(v.y), f2tf32(v.z), f2tf32(v.w));
        *(uint4*)(vsr + kk * VSTR + c4 * 4) = u;
    }
    // p-pass: thread owns (qi_p, k0p..k0p+15)
    const float* rp = g_rinv + (size_t)(q0 + qi_p) * SEQ + kb + k0p;
    const float* mk = mrow + kb + k0p;
    float psum = 0.0f;
    #pragma unroll
    for (int j4 = 0; j4 < 4; j4++) {
        float4 rv = *(const float4*)(rp + j4 * 4);
        float4 mv = *(const float4*)(mk + j4 * 4);
        float e0 = __expf(fminf(mq * mv.x * rv.x, 50.0f) - 50.0f);
        float e1 = __expf(fminf(mq * mv.y * rv.y, 50.0f) - 50.0f);
        float e2 = __expf(fminf(mq * mv.z * rv.z, 50.0f) - 50.0f);
        float e3 = __expf(fminf(mq * mv.w * rv.w, 50.0f) - 50.0f);
        psum += (e0 + e1) + (e2 + e3);
        uint4 u = make_uint4(f2tf32(e0), f2tf32(e1), f2tf32(e2), f2tf32(e3));
        *(uint4*)(ps + qi_p * PSTR + k0p + j4 * 4) = u;
    }
    psum += __shfl_xor_sync(0xFFFFFFFFu, psum, 1);
    psum += __shfl_xor_sync(0xFFFFFFFFu, psum, 2);
    if (part == 0) denr += psum;
}

__global__ __launch_bounds__(256) void attn_kernel() {
    extern __shared__ float smem[];
    float* den_s = smem + 2 * BUFSZ;

    const int bh = blockIdx.y;
    const int b  = bh >> 3;
    const int h  = bh & (HEADS - 1);
    const int q0 = blockIdx.x * 64;
    const int t  = threadIdx.x;
    const int warp = t >> 5, lane = t & 31;
    const int g = lane >> 2, tig = lane & 3;
    const int wm = warp >> 2, wn = warp & 3;   // 2 x 4 warp grid
    const int qi_p = t >> 2, part = t & 3;
    const int k0p  = part * 16;

    const float* mrow = g_masses + (size_t)bh * SEQ;
    const float  mq   = mrow[q0 + qi_p];
    float denr = 0.0f;

    float acc[2][4][4];
    #pragma unroll
    for (int mt = 0; mt < 2; mt++)
        #pragma unroll
        for (int nt = 0; nt < 4; nt++)
            #pragma unroll
            for (int c = 0; c < 4; c++) acc[mt][nt][c] = 0.0f;

    attn_fill(smem, smem + KC * VSTR, b, h, 0, t, mrow, q0, qi_p, k0p, mq, denr, part);

    constexpr int NCH = SEQ / KC;   // 32
    for (int i = 0; i < NCH; i++) {
        __syncthreads();
        if (i + 1 < NCH) {
            float* nb = smem + ((i + 1) & 1) * BUFSZ;
            attn_fill(nb, nb + KC * VSTR, b, h, (i + 1) * KC, t,
                      mrow, q0, qi_p, k0p, mq, denr, part);
        }
        const float* vsr = smem + (i & 1) * BUFSZ;
        const float* ps  = vsr + KC * VSTR;
        #pragma unroll
        for (int ks = 0; ks < 8; ks++) {
            int kk = ks * 8;
            uint32_t af[2][4];
            #pragma unroll
            for (int mt = 0; mt < 2; mt++) {
                int r = wm * 32 + mt * 16;
                const uint32_t* prow  = (const uint32_t*)(ps + (r + g) * PSTR + kk);
                const uint32_t* prow8 = (const uint32_t*)(ps + (r + g + 8) * PSTR + kk);
                af[mt][0] = prow[tig];
                af[mt][1] = prow8[tig];
                af[mt][2] = prow[tig + 4];
                af[mt][3] = prow8[tig + 4];
            }
            uint32_t bf[4][2];
            #pragma unroll
            for (int nt = 0; nt < 4; nt++) {
                int c = wn * 32 + nt * 8;
                bf[nt][0] = ((const uint32_t*)vsr)[(kk + tig) * VSTR + c + g];
                bf[nt][1] = ((const uint32_t*)vsr)[(kk + tig + 4) * VSTR + c + g];
            }
            #pragma unroll
            for (int mt = 0; mt < 2; mt++)
                #pragma unroll
                for (int nt = 0; nt < 4; nt++) {
                    asm volatile(
                        "mma.sync.aligned.m16n8k8.row.col.f32.tf32.tf32.f32 "
                        "{%0,%1,%2,%3}, {%4,%5,%6,%7}, {%8,%9}, {%0,%1,%2,%3};"
                        : "+f"(acc[mt][nt][0]), "+f"(acc[mt][nt][1]),
                          "+f"(acc[mt][nt][2]), "+f"(acc[mt][nt][3])
                        : "r"(af[mt][0]), "r"(af[mt][1]), "r"(af[mt][2]), "r"(af[mt][3]),
                          "r"(bf[nt][0]), "r"(bf[nt][1]));
                }
        }
    }
    if (part == 0) den_s[qi_p] = denr;
    __syncthreads();
    #pragma unroll
    for (int mt = 0; mt < 2; mt++) {
        int r = wm * 32 + mt * 16 + g;
        float rd0 = 1.0f / den_s[r];
        float rd8 = 1.0f / den_s[r + 8];
        #pragma unroll
        for (int nt = 0; nt < 4; nt++) {
            int col = h * HD + wn * 32 + nt * 8 + 2 * tig;
            size_t row = (size_t)(b * SEQ + q0 + r);
            *(float2*)(g_ho + row * DIM + col) =
                make_float2(acc[mt][nt][0] * rd0, acc[mt][nt][1] * rd0);
            *(float2*)(g_ho + (row + 8) * DIM + col) =
                make_float2(acc[mt][nt][2] * rd8, acc[mt][nt][3] * rd8);
        }
    }
}

// ---------------------------------------------------------------------------
extern "C" void kernel_launch(void* const* d_in, const int* in_sizes, int n_in,
                              void* d_out, int out_size) {
    const float* x      = (const float*)d_in[0];
    const float* mass_w = (const float*)d_in[1];
    const float* v_w    = (const float*)d_in[2];
    const float* out_w  = (const float*)d_in[3];
    const float* pos    = (const float*)d_in[4];
    float* out = (float*)d_out;

    float *pv = nullptr, *pho = nullptr;
    cudaGetSymbolAddress((void**)&pv,  g_v);
    cudaGetSymbolAddress((void**)&pho, g_ho);
    cudaFuncSetAttribute(attn_kernel,
                         cudaFuncAttributeMaxDynamicSharedMemorySize, ATTN_SMEM_BYTES);

    dist_kernel<<<(SEQ * SEQ) / 256, 256>>>(pos);
    masses_kernel<<<(BATCH * SEQ * HEADS * 32) / 256, 256>>>(x, mass_w);
    gemm_tf32<<<dim3(DIM / 128, M_ROWS / 128), 256>>>(x, v_w, pv);
    attn_kernel<<<dim3(SEQ / 64, BATCH * HEADS), 256, ATTN_SMEM_BYTES>>>();
    gemm_tf32<<<dim3(DIM / 128, M_ROWS / 128), 256>>>(pho, out_w, out);
}

// round 9
// speedup vs baseline: 2.9614x; 1.0388x over previous
#include <cuda_runtime.h>
#include <cuda_bf16.h>
#include <math.h>
#include <stdint.h>

constexpr int BATCH = 2;
constexpr int SEQ   = 2048;
constexpr int DIM   = 1024;
constexpr int HEADS = 8;
constexpr int HD    = 128;
constexpr int M_ROWS = BATCH * SEQ;  // 4096

__device__ float g_rinv[SEQ * SEQ];
__device__ float g_masses[BATCH * HEADS * SEQ];
__device__ float g_v[M_ROWS * DIM];
__device__ float g_ho[M_ROWS * DIM];

__device__ __forceinline__ uint32_t f2tf32(float x) {
    uint32_t u;
    asm("cvt.rna.tf32.f32 %0, %1;" : "=r"(u) : "f"(x));
    return u;
}

// ---------------------------------------------------------------------------
// Kernel 1: rinv
// ---------------------------------------------------------------------------
__global__ __launch_bounds__(256) void dist_kernel(const float* __restrict__ pe) {
    int idx = blockIdx.x * 256 + threadIdx.x;
    int q = idx >> 11;
    int k = idx & (SEQ - 1);
    const float4* P = (const float4*)pe;
    float4 qa = P[q * 2], qb = P[q * 2 + 1];
    float4 ka = P[k * 2], kb = P[k * 2 + 1];
    float dx0 = qa.x - ka.x, dx1 = qa.y - ka.y, dx2 = qa.z - ka.z, dx3 = qa.w - ka.w;
    float dx4 = qb.x - kb.x, dx5 = qb.y - kb.y, dx6 = qb.z - kb.z, dx7 = qb.w - kb.w;
    float ss = dx0*dx0 + dx1*dx1 + dx2*dx2 + dx3*dx3
             + dx4*dx4 + dx5*dx5 + dx6*dx6 + dx7*dx7;
    float d = sqrtf(ss + 1e-12f);
    d = d * (1.0f + 0.15f * sinf(d));
    d = fmaxf(d, 0.0f);
    g_rinv[idx] = 1.0f / (d * d + 1e-6f);
}

// ---------------------------------------------------------------------------
// Kernel 2: masses
// ---------------------------------------------------------------------------
__global__ __launch_bounds__(256) void masses_kernel(const float* __restrict__ x,
                                                     const float* __restrict__ mw) {
    int warp = (blockIdx.x * 256 + threadIdx.x) >> 5;
    int lane = threadIdx.x & 31;
    int h  = warp & (HEADS - 1);
    int bs = warp >> 3;
    const float4* xp = (const float4*)(x + (size_t)bs * DIM + h * HD);
    const float4* wp = (const float4*)(mw + h * HD);
    float4 xv = xp[lane];
    float4 wv = wp[lane];
    float s = xv.x*wv.x + xv.y*wv.y + xv.z*wv.z + xv.w*wv.w;
    #pragma unroll
    for (int o = 16; o; o >>= 1) s += __shfl_xor_sync(0xFFFFFFFFu, s, o);
    if (lane == 0) {
        int b = bs >> 11, ss = bs & (SEQ - 1);
        g_masses[((size_t)b * HEADS + h) * SEQ + ss] = 1.0f / (1.0f + __expf(-s));
    }
}

// ---------------------------------------------------------------------------
// Kernels 3/5: tf32 tensor-core GEMM, double-buffered (unchanged from R8)
// ---------------------------------------------------------------------------
constexpr int GBK = 16;

__device__ __forceinline__ void gemm_fill(uint32_t (*Asb)[GBK + 4],
                                          uint32_t (*Wsb)[GBK + 4],
                                          const float* __restrict__ A,
                                          const float* __restrict__ W,
                                          int bm, int bn, int k0, int t) {
    #pragma unroll
    for (int i = 0; i < 2; i++) {
        int idx = t + i * 256;
        int row = idx >> 2, seg = (idx & 3) * 4;
        float4 a = *(const float4*)(A + (size_t)(bm + row) * DIM + k0 + seg);
        float4 w = *(const float4*)(W + (size_t)(bn + row) * DIM + k0 + seg);
        Asb[row][seg + 0] = f2tf32(a.x); Asb[row][seg + 1] = f2tf32(a.y);
        Asb[row][seg + 2] = f2tf32(a.z); Asb[row][seg + 3] = f2tf32(a.w);
        Wsb[row][seg + 0] = f2tf32(w.x); Wsb[row][seg + 1] = f2tf32(w.y);
        Wsb[row][seg + 2] = f2tf32(w.z); Wsb[row][seg + 3] = f2tf32(w.w);
    }
}

__global__ __launch_bounds__(256) void gemm_tf32(const float* __restrict__ A,
                                                 const float* __restrict__ W,
                                                 float* __restrict__ C) {
    __shared__ uint32_t As[2][128][GBK + 4];
    __shared__ uint32_t Ws[2][128][GBK + 4];
    const int t    = threadIdx.x;
    const int warp = t >> 5, lane = t & 31;
    const int wm = warp >> 1, wn = warp & 1;
    const int g  = lane >> 2, tig = lane & 3;
    const int bm = blockIdx.y * 128, bn = blockIdx.x * 128;

    float acc[2][8][4];
    #pragma unroll
    for (int mt = 0; mt < 2; mt++)
        #pragma unroll
        for (int nt = 0; nt < 8; nt++)
            #pragma unroll
            for (int c = 0; c < 4; c++) acc[mt][nt][c] = 0.0f;

    gemm_fill(As[0], Ws[0], A, W, bm, bn, 0, t);

    constexpr int NIT = DIM / GBK;
    for (int i = 0; i < NIT; i++) {
        __syncthreads();
        if (i + 1 < NIT)
            gemm_fill(As[(i + 1) & 1], Ws[(i + 1) & 1], A, W, bm, bn, (i + 1) * GBK, t);
        uint32_t (*Ab)[GBK + 4] = As[i & 1];
        uint32_t (*Wb)[GBK + 4] = Ws[i & 1];
        #pragma unroll
        for (int kk = 0; kk < GBK; kk += 8) {
            uint32_t af[2][4];
            #pragma unroll
            for (int mt = 0; mt < 2; mt++) {
                int r = wm * 32 + mt * 16;
                af[mt][0] = Ab[r + g][kk + tig];
                af[mt][1] = Ab[r + g + 8][kk + tig];
                af[mt][2] = Ab[r + g][kk + tig + 4];
                af[mt][3] = Ab[r + g + 8][kk + tig + 4];
            }
            uint32_t bf[8][2];
            #pragma unroll
            for (int nt = 0; nt < 8; nt++) {
                int c = wn * 64 + nt * 8;
                bf[nt][0] = Wb[c + g][kk + tig];
                bf[nt][1] = Wb[c + g][kk + tig + 4];
            }
            #pragma unroll
            for (int mt = 0; mt < 2; mt++)
                #pragma unroll
                for (int nt = 0; nt < 8; nt++) {
                    asm volatile(
                        "mma.sync.aligned.m16n8k8.row.col.f32.tf32.tf32.f32 "
                        "{%0,%1,%2,%3}, {%4,%5,%6,%7}, {%8,%9}, {%0,%1,%2,%3};"
                        : "+f"(acc[mt][nt][0]), "+f"(acc[mt][nt][1]),
                          "+f"(acc[mt][nt][2]), "+f"(acc[mt][nt][3])
                        : "r"(af[mt][0]), "r"(af[mt][1]), "r"(af[mt][2]), "r"(af[mt][3]),
                          "r"(bf[nt][0]), "r"(bf[nt][1]));
                }
        }
    }
    #pragma unroll
    for (int mt = 0; mt < 2; mt++) {
        #pragma unroll
        for (int nt = 0; nt < 8; nt++) {
            size_t r0 = (size_t)(bm + wm * 32 + mt * 16 + g);
            int col = bn + wn * 64 + nt * 8 + 2 * tig;
            *(float2*)(C + r0 * DIM + col) =
                make_float2(acc[mt][nt][0], acc[mt][nt][1]);
            *(float2*)(C + (r0 + 8) * DIM + col) =
                make_float2(acc[mt][nt][2], acc[mt][nt][3]);
        }
    }
}

// ---------------------------------------------------------------------------
// Kernel 4: fused force->softmax->@V, tf32 mma PV.
// Single-buffer smem (52.5KB) + __launch_bounds__(256,3) -> 3 blocks/SM.
// V staged via cp.async (raw fp32 bits; HMMA.TF32 truncates low mantissa).
// ---------------------------------------------------------------------------
constexpr int KC = 64;
constexpr int VSTR = 136;
constexpr int PSTR = 68;
constexpr int ATTN_SMEM_FLOATS = KC * VSTR + 64 * PSTR + 64;
constexpr int ATTN_SMEM_BYTES  = ATTN_SMEM_FLOATS * 4;   // 52480

__global__ __launch_bounds__(256, 3) void attn_kernel() {
    extern __shared__ float smem[];
    float* vsr   = smem;                    // [KC][VSTR] fp32 bits (tf32-truncated by mma)
    float* ps    = vsr + KC * VSTR;         // [64][PSTR] tf32 (rna)
    float* den_s = ps + 64 * PSTR;          // [64]

    const int bh = blockIdx.y;
    const int b  = bh >> 3;
    const int h  = bh & (HEADS - 1);
    const int q0 = blockIdx.x * 64;
    const int t  = threadIdx.x;
    const int warp = t >> 5, lane = t & 31;
    const int g = lane >> 2, tig = lane & 3;
    const int wm = warp >> 2, wn = warp & 3;   // 2 x 4 warp grid
    const int qi_p = t >> 2, part = t & 3;
    const int k0p  = part * 16;

    const float* mrow = g_masses + (size_t)bh * SEQ;
    const float  mq   = mrow[q0 + qi_p];
    float denr = 0.0f;

    // precomputed cp.async smem dst addresses (8 x 16B per thread)
    const int vkk = t >> 5;       // base row handled by this thread's slot: e>>5 pattern
    const int vc4 = t & 31;
    uint32_t vdst_base = (uint32_t)__cvta_generic_to_shared(vsr);

    float acc[2][4][4];
    #pragma unroll
    for (int mt = 0; mt < 2; mt++)
        #pragma unroll
        for (int nt = 0; nt < 4; nt++)
            #pragma unroll
            for (int c = 0; c < 4; c++) acc[mt][nt][c] = 0.0f;

    constexpr int NCH = SEQ / KC;   // 32
    for (int i = 0; i < NCH; i++) {
        const int kb = i * KC;
        // --- V stage via cp.async: 8 x 16B per thread ---
        #pragma unroll
        for (int j = 0; j < 8; j++) {
            int kk = vkk + j * 8;            // (t + j*256)>>5
            uint32_t dst = vdst_base + (uint32_t)((kk * VSTR + vc4 * 4) * 4);
            const float* src = g_v + ((size_t)(b * SEQ + kb + kk)) * DIM + h * HD + vc4 * 4;
            asm volatile("cp.async.ca.shared.global [%0], [%1], 16;\n"
                         :: "r"(dst), "l"(src));
        }
        // --- p-pass (overlaps cp.async flight) ---
        {
            const float* rp = g_rinv + (size_t)(q0 + qi_p) * SEQ + kb + k0p;
            const float* mk = mrow + kb + k0p;
            float psum = 0.0f;
            #pragma unroll
            for (int j4 = 0; j4 < 4; j4++) {
                float4 rv = *(const float4*)(rp + j4 * 4);
                float4 mv = *(const float4*)(mk + j4 * 4);
                float e0 = __expf(fminf(mq * mv.x * rv.x, 50.0f) - 50.0f);
                float e1 = __expf(fminf(mq * mv.y * rv.y, 50.0f) - 50.0f);
                float e2 = __expf(fminf(mq * mv.z * rv.z, 50.0f) - 50.0f);
                float e3 = __expf(fminf(mq * mv.w * rv.w, 50.0f) - 50.0f);
                psum += (e0 + e1) + (e2 + e3);
                uint4 u = make_uint4(f2tf32(e0), f2tf32(e1), f2tf32(e2), f2tf32(e3));
                *(uint4*)(ps + qi_p * PSTR + k0p + j4 * 4) = u;
            }
            psum += __shfl_xor_sync(0xFFFFFFFFu, psum, 1);
            psum += __shfl_xor_sync(0xFFFFFFFFu, psum, 2);
            if (part == 0) denr += psum;
        }
        asm volatile("cp.async.wait_all;\n" ::: "memory");
        __syncthreads();
        // --- PV mma ---
        #pragma unroll
        for (int ks = 0; ks < 8; ks++) {
            int kk = ks * 8;
            uint32_t af[2][4];
            #pragma unroll
            for (int mt = 0; mt < 2; mt++) {
                int r = wm * 32 + mt * 16;
                const uint32_t* prow  = (const uint32_t*)(ps + (r + g) * PSTR + kk);
                const uint32_t* prow8 = (const uint32_t*)(ps + (r + g + 8) * PSTR + kk);
                af[mt][0] = prow[tig];
                af[mt][1] = prow8[tig];
                af[mt][2] = prow[tig + 4];
                af[mt][3] = prow8[tig + 4];
            }
            uint32_t bf[4][2];
            #pragma unroll
            for (int nt = 0; nt < 4; nt++) {
                int c = wn * 32 + nt * 8;
                bf[nt][0] = ((const uint32_t*)vsr)[(kk + tig) * VSTR + c + g];
                bf[nt][1] = ((const uint32_t*)vsr)[(kk + tig + 4) * VSTR + c + g];
            }
            #pragma unroll
            for (int mt = 0; mt < 2; mt++)
                #pragma unroll
                for (int nt = 0; nt < 4; nt++) {
                    asm volatile(
                        "mma.sync.aligned.m16n8k8.row.col.f32.tf32.tf32.f32 "
                        "{%0,%1,%2,%3}, {%4,%5,%6,%7}, {%8,%9}, {%0,%1,%2,%3};"
                        : "+f"(acc[mt][nt][0]), "+f"(acc[mt][nt][1]),
                          "+f"(acc[mt][nt][2]), "+f"(acc[mt][nt][3])
                        : "r"(af[mt][0]), "r"(af[mt][1]), "r"(af[mt][2]), "r"(af[mt][3]),
                          "r"(bf[nt][0]), "r"(bf[nt][1]));
                }
        }
        __syncthreads();
    }
    if (part == 0) den_s[qi_p] = denr;
    __syncthreads();
    #pragma unroll
    for (int mt = 0; mt < 2; mt++) {
        int r = wm * 32 + mt * 16 + g;
        float rd0 = 1.0f / den_s[r];
        float rd8 = 1.0f / den_s[r + 8];
        #pragma unroll
        for (int nt = 0; nt < 4; nt++) {
            int col = h * HD + wn * 32 + nt * 8 + 2 * tig;
            size_t row = (size_t)(b * SEQ + q0 + r);
            *(float2*)(g_ho + row * DIM + col) =
                make_float2(acc[mt][nt][0] * rd0, acc[mt][nt][1] * rd0);
            *(float2*)(g_ho + (row + 8) * DIM + col) =
                make_float2(acc[mt][nt][2] * rd8, acc[mt][nt][3] * rd8);
        }
    }
}

// ---------------------------------------------------------------------------
extern "C" void kernel_launch(void* const* d_in, const int* in_sizes, int n_in,
                              void* d_out, int out_size) {
    const float* x      = (const float*)d_in[0];
    const float* mass_w = (const float*)d_in[1];
    const float* v_w    = (const float*)d_in[2];
    const float* out_w  = (const float*)d_in[3];
    const float* pos    = (const float*)d_in[4];
    float* out = (float*)d_out;

    float *pv = nullptr, *pho = nullptr;
    cudaGetSymbolAddress((void**)&pv,  g_v);
    cudaGetSymbolAddress((void**)&pho, g_ho);
    cudaFuncSetAttribute(attn_kernel,
                         cudaFuncAttributeMaxDynamicSharedMemorySize, ATTN_SMEM_BYTES);

    dist_kernel<<<(SEQ * SEQ) / 256, 256>>>(pos);
    masses_kernel<<<(BATCH * SEQ * HEADS * 32) / 256, 256>>>(x, mass_w);
    gemm_tf32<<<dim3(DIM / 128, M_ROWS / 128), 256>>>(x, v_w, pv);
    attn_kernel<<<dim3(SEQ / 64, BATCH * HEADS), 256, ATTN_SMEM_BYTES>>>();
    gemm_tf32<<<dim3(DIM / 128, M_ROWS / 128), 256>>>(pho, out_w, out);
}

// round 10
// speedup vs baseline: 3.4016x; 1.1486x over previous
#include <cuda_runtime.h>
#include <cuda_fp16.h>
#include <math.h>
#include <stdint.h>

constexpr int BATCH = 2;
constexpr int SEQ   = 2048;
constexpr int DIM   = 1024;
constexpr int HEADS = 8;
constexpr int HD    = 128;
constexpr int M_ROWS = BATCH * SEQ;  // 4096
constexpr int BH    = BATCH * HEADS; // 16

__device__ float  g_rinv[SEQ * SEQ];                 // 16 MB
__device__ float  g_masses[BH * SEQ];
__device__ __half g_vh[M_ROWS * DIM];                // 8 MB (fp16 V)
__device__ float  g_ho[M_ROWS * DIM];                // 16 MB
__device__ __half g_p[(size_t)BH * SEQ * SEQ];       // 128 MB (fp16 P)
__device__ float  g_den[BH * SEQ];

__device__ __forceinline__ uint32_t f2tf32(float x) {
    uint32_t u;
    asm("cvt.rna.tf32.f32 %0, %1;" : "=r"(u) : "f"(x));
    return u;
}

// ---------------------------------------------------------------------------
// Kernel 1: rinv
// ---------------------------------------------------------------------------
__global__ __launch_bounds__(256) void dist_kernel(const float* __restrict__ pe) {
    int idx = blockIdx.x * 256 + threadIdx.x;
    int q = idx >> 11;
    int k = idx & (SEQ - 1);
    const float4* P = (const float4*)pe;
    float4 qa = P[q * 2], qb = P[q * 2 + 1];
    float4 ka = P[k * 2], kb = P[k * 2 + 1];
    float dx0 = qa.x - ka.x, dx1 = qa.y - ka.y, dx2 = qa.z - ka.z, dx3 = qa.w - ka.w;
    float dx4 = qb.x - kb.x, dx5 = qb.y - kb.y, dx6 = qb.z - kb.z, dx7 = qb.w - kb.w;
    float ss = dx0*dx0 + dx1*dx1 + dx2*dx2 + dx3*dx3
             + dx4*dx4 + dx5*dx5 + dx6*dx6 + dx7*dx7;
    float d = sqrtf(ss + 1e-12f);
    d = d * (1.0f + 0.15f * sinf(d));
    d = fmaxf(d, 0.0f);
    g_rinv[idx] = 1.0f / (d * d + 1e-6f);
}

// ---------------------------------------------------------------------------
// Kernel 2: masses
// ---------------------------------------------------------------------------
__global__ __launch_bounds__(256) void masses_kernel(const float* __restrict__ x,
                                                     const float* __restrict__ mw) {
    int warp = (blockIdx.x * 256 + threadIdx.x) >> 5;
    int lane = threadIdx.x & 31;
    int h  = warp & (HEADS - 1);
    int bs = warp >> 3;
    const float4* xp = (const float4*)(x + (size_t)bs * DIM + h * HD);
    const float4* wp = (const float4*)(mw + h * HD);
    float4 xv = xp[lane];
    float4 wv = wp[lane];
    float s = xv.x*wv.x + xv.y*wv.y + xv.z*wv.z + xv.w*wv.w;
    #pragma unroll
    for (int o = 16; o; o >>= 1) s += __shfl_xor_sync(0xFFFFFFFFu, s, o);
    if (lane == 0) {
        int b = bs >> 11, ss = bs & (SEQ - 1);
        g_masses[(b * HEADS + h) * SEQ + ss] = 1.0f / (1.0f + __expf(-s));
    }
}

// ---------------------------------------------------------------------------
// Kernels 3/5: tf32 tensor-core GEMM (double-buffered). HALF_OUT selects
// fp16 epilogue (V gemm) vs fp32 (out gemm).
// ---------------------------------------------------------------------------
constexpr int GBK = 16;

__device__ __forceinline__ void gemm_fill(uint32_t (*Asb)[GBK + 4],
                                          uint32_t (*Wsb)[GBK + 4],
                                          const float* __restrict__ A,
                                          const float* __restrict__ W,
                                          int bm, int bn, int k0, int t) {
    #pragma unroll
    for (int i = 0; i < 2; i++) {
        int idx = t + i * 256;
        int row = idx >> 2, seg = (idx & 3) * 4;
        float4 a = *(const float4*)(A + (size_t)(bm + row) * DIM + k0 + seg);
        float4 w = *(const float4*)(W + (size_t)(bn + row) * DIM + k0 + seg);
        Asb[row][seg + 0] = f2tf32(a.x); Asb[row][seg + 1] = f2tf32(a.y);
        Asb[row][seg + 2] = f2tf32(a.z); Asb[row][seg + 3] = f2tf32(a.w);
        Wsb[row][seg + 0] = f2tf32(w.x); Wsb[row][seg + 1] = f2tf32(w.y);
        Wsb[row][seg + 2] = f2tf32(w.z); Wsb[row][seg + 3] = f2tf32(w.w);
    }
}

template <bool HALF_OUT>
__global__ __launch_bounds__(256) void gemm_tf32(const float* __restrict__ A,
                                                 const float* __restrict__ W,
                                                 void* __restrict__ Cv) {
    __shared__ uint32_t As[2][128][GBK + 4];
    __shared__ uint32_t Ws[2][128][GBK + 4];
    const int t    = threadIdx.x;
    const int warp = t >> 5, lane = t & 31;
    const int wm = warp >> 1, wn = warp & 1;
    const int g  = lane >> 2, tig = lane & 3;
    const int bm = blockIdx.y * 128, bn = blockIdx.x * 128;

    float acc[2][8][4];
    #pragma unroll
    for (int mt = 0; mt < 2; mt++)
        #pragma unroll
        for (int nt = 0; nt < 8; nt++)
            #pragma unroll
            for (int c = 0; c < 4; c++) acc[mt][nt][c] = 0.0f;

    gemm_fill(As[0], Ws[0], A, W, bm, bn, 0, t);

    constexpr int NIT = DIM / GBK;
    for (int i = 0; i < NIT; i++) {
        __syncthreads();
        if (i + 1 < NIT)
            gemm_fill(As[(i + 1) & 1], Ws[(i + 1) & 1], A, W, bm, bn, (i + 1) * GBK, t);
        uint32_t (*Ab)[GBK + 4] = As[i & 1];
        uint32_t (*Wb)[GBK + 4] = Ws[i & 1];
        #pragma unroll
        for (int kk = 0; kk < GBK; kk += 8) {
            uint32_t af[2][4];
            #pragma unroll
            for (int mt = 0; mt < 2; mt++) {
                int r = wm * 32 + mt * 16;
                af[mt][0] = Ab[r + g][kk + tig];
                af[mt][1] = Ab[r + g + 8][kk + tig];
                af[mt][2] = Ab[r + g][kk + tig + 4];
                af[mt][3] = Ab[r + g + 8][kk + tig + 4];
            }
            uint32_t bf[8][2];
            #pragma unroll
            for (int nt = 0; nt < 8; nt++) {
                int c = wn * 64 + nt * 8;
                bf[nt][0] = Wb[c + g][kk + tig];
                bf[nt][1] = Wb[c + g][kk + tig + 4];
            }
            #pragma unroll
            for (int mt = 0; mt < 2; mt++)
                #pragma unroll
                for (int nt = 0; nt < 8; nt++) {
                    asm volatile(
                        "mma.sync.aligned.m16n8k8.row.col.f32.tf32.tf32.f32 "
                        "{%0,%1,%2,%3}, {%4,%5,%6,%7}, {%8,%9}, {%0,%1,%2,%3};"
                        : "+f"(acc[mt][nt][0]), "+f"(acc[mt][nt][1]),
                          "+f"(acc[mt][nt][2]), "+f"(acc[mt][nt][3])
                        : "r"(af[mt][0]), "r"(af[mt][1]), "r"(af[mt][2]), "r"(af[mt][3]),
                          "r"(bf[nt][0]), "r"(bf[nt][1]));
                }
        }
    }
    #pragma unroll
    for (int mt = 0; mt < 2; mt++) {
        #pragma unroll
        for (int nt = 0; nt < 8; nt++) {
            size_t r0 = (size_t)(bm + wm * 32 + mt * 16 + g);
            int col = bn + wn * 64 + nt * 8 + 2 * tig;
            if (HALF_OUT) {
                __half* C = (__half*)Cv;
                *(__half2*)(C + r0 * DIM + col) =
                    __floats2half2_rn(acc[mt][nt][0], acc[mt][nt][1]);
                *(__half2*)(C + (r0 + 8) * DIM + col) =
                    __floats2half2_rn(acc[mt][nt][2], acc[mt][nt][3]);
            } else {
                float* C = (float*)Cv;
                *(float2*)(C + r0 * DIM + col) =
                    make_float2(acc[mt][nt][0], acc[mt][nt][1]);
                *(float2*)(C + (r0 + 8) * DIM + col) =
                    make_float2(acc[mt][nt][2], acc[mt][nt][3]);
            }
        }
    }
}

// ---------------------------------------------------------------------------
// Kernel 4a: pgen — P[bh][q][k] = fp16(exp(min(mq*mk*rinv,50)-50)),
// den[bh][q] = fp32 row sum (from unrounded values).
// Grid (SEQ/64, BH), 256 threads: thread = (qi = t>>2, part = t&3).
// ---------------------------------------------------------------------------
__global__ __launch_bounds__(256) void pgen_kernel() {
    const int bh = blockIdx.y;
    const int q0 = blockIdx.x * 64;
    const int t  = threadIdx.x;
    const int qi = q0 + (t >> 2), part = t & 3;
    const int k0p = part * 16;

    const float* mrow = g_masses + bh * SEQ;
    const float  mq   = mrow[qi];
    const float* rrow = g_rinv + (size_t)qi * SEQ;
    __half* prow = g_p + ((size_t)bh * SEQ + qi) * SEQ;

    float denr = 0.0f;
    for (int kb = 0; kb < SEQ; kb += 64) {
        const float* rp = rrow + kb + k0p;
        const float* mk = mrow + kb + k0p;
        #pragma unroll
        for (int j4 = 0; j4 < 4; j4++) {
            float4 rv = *(const float4*)(rp + j4 * 4);
            float4 mv = *(const float4*)(mk + j4 * 4);
            float e0 = __expf(fminf(mq * mv.x * rv.x, 50.0f) - 50.0f);
            float e1 = __expf(fminf(mq * mv.y * rv.y, 50.0f) - 50.0f);
            float e2 = __expf(fminf(mq * mv.z * rv.z, 50.0f) - 50.0f);
            float e3 = __expf(fminf(mq * mv.w * rv.w, 50.0f) - 50.0f);
            denr += (e0 + e1) + (e2 + e3);
            __half2 h01 = __floats2half2_rn(e0, e1);
            __half2 h23 = __floats2half2_rn(e2, e3);
            *(uint2*)(prow + kb + k0p + j4 * 4) =
                make_uint2(*(uint32_t*)&h01, *(uint32_t*)&h23);
        }
    }
    denr += __shfl_xor_sync(0xFFFFFFFFu, denr, 1);
    denr += __shfl_xor_sync(0xFFFFFFFFu, denr, 2);
    if (part == 0) g_den[bh * SEQ + qi] = denr;
}

// ---------------------------------------------------------------------------
// Kernel 4b: attn_gemm — head_out = (P @ V_h) / den, fp16 m16n8k16.
// Tile: 128 q x 128 hd, K chunks of 64. 8 warps (4m x 2n), warp 32x64.
// P via ldmatrix.x4, V via ldmatrix.x4.trans (V stays [k][c] layout).
// cp.async double-buffered.
// ---------------------------------------------------------------------------
constexpr int KCH   = 64;
constexpr int PSTRH = 72;    // halfs per P row (64+8): 144B ≡ 4 words mod 32
constexpr int VSTRH = 136;   // halfs per V row (128+8): 272B ≡ 4 words mod 32
constexpr int PBUF  = 128 * PSTRH;   // 9216 halfs
constexpr int VBUF  = KCH * VSTRH;   // 8704 halfs
constexpr int ATTN2_SMEM_BYTES = 2 * (PBUF + VBUF) * 2;  // 71680

__device__ __forceinline__ void ldm_x4(uint32_t& r0, uint32_t& r1,
                                       uint32_t& r2, uint32_t& r3, uint32_t a) {
    asm volatile("ldmatrix.sync.aligned.m8n8.x4.shared.b16 {%0,%1,%2,%3}, [%4];"
                 : "=r"(r0), "=r"(r1), "=r"(r2), "=r"(r3) : "r"(a));
}
__device__ __forceinline__ void ldm_x4_t(uint32_t& r0, uint32_t& r1,
                                         uint32_t& r2, uint32_t& r3, uint32_t a) {
    asm volatile("ldmatrix.sync.aligned.m8n8.x4.trans.shared.b16 {%0,%1,%2,%3}, [%4];"
                 : "=r"(r0), "=r"(r1), "=r"(r2), "=r"(r3) : "r"(a));
}

__device__ __forceinline__ void attn2_stage(__half* pb, __half* vb,
                                            int bh, int b, int h,
                                            int q0, int kb, int t) {
    uint32_t pdst = (uint32_t)__cvta_generic_to_shared(pb);
    uint32_t vdst = (uint32_t)__cvta_generic_to_shared(vb);
    #pragma unroll
    for (int i = 0; i < 4; i++) {           // P tile: 128 rows x 64 halfs
        int e = t + i * 256;
        int row = e >> 3, seg = e & 7;
        const __half* src = g_p + ((size_t)bh * SEQ + q0 + row) * SEQ + kb + seg * 8;
        asm volatile("cp.async.ca.shared.global [%0], [%1], 16;\n"
                     :: "r"(pdst + (uint32_t)((row * PSTRH + seg * 8) * 2)), "l"(src));
    }
    #pragma unroll
    for (int i = 0; i < 4; i++) {           // V tile: 64 rows x 128 halfs
        int e = t + i * 256;
        int row = e >> 4, seg = e & 15;
        const __half* src = g_vh + ((size_t)(b * SEQ + kb + row)) * DIM + h * HD + seg * 8;
        asm volatile("cp.async.ca.shared.global [%0], [%1], 16;\n"
                     :: "r"(vdst + (uint32_t)((row * VSTRH + seg * 8) * 2)), "l"(src));
    }
    asm volatile("cp.async.commit_group;\n" ::: "memory");
}

__global__ __launch_bounds__(256) void attn_gemm() {
    extern __shared__ __half smh[];
    const int bh = blockIdx.y;
    const int b  = bh >> 3;
    const int h  = bh & (HEADS - 1);
    const int q0 = blockIdx.x * 128;
    const int t  = threadIdx.x;
    const int warp = t >> 5, lane = t & 31;
    const int g = lane >> 2, tig = lane & 3;
    const int wm = warp >> 1, wn = warp & 1;     // 4m x 2n

    float acc[2][8][4];
    #pragma unroll
    for (int mt = 0; mt < 2; mt++)
        #pragma unroll
        for (int nt = 0; nt < 8; nt++)
            #pragma unroll
            for (int c = 0; c < 4; c++) acc[mt][nt][c] = 0.0f;

    // ldmatrix lane address components
    const int aRow = lane & 15, aColOff = (lane >> 4) << 3;            // A
    const int bRow = (lane & 7) + (((lane >> 3) & 1) << 3);            // B (trans)
    const int bColOff = (lane >> 4) << 3;

    attn2_stage(smh, smh + PBUF, bh, b, h, q0, 0, t);

    constexpr int NCH = SEQ / KCH;   // 32
    for (int i = 0; i < NCH; i++) {
        if (i + 1 < NCH) {
            __half* nb = smh + ((i + 1) & 1) * (PBUF + VBUF);
            attn2_stage(nb, nb + PBUF, bh, b, h, q0, (i + 1) * KCH, t);
            asm volatile("cp.async.wait_group 1;\n" ::: "memory");
        } else {
            asm volatile("cp.async.wait_group 0;\n" ::: "memory");
        }
        __syncthreads();
        const __half* pb = smh + (i & 1) * (PBUF + VBUF);
        const __half* vb = pb + PBUF;
        uint32_t pbase = (uint32_t)__cvta_generic_to_shared(pb);
        uint32_t vbase = (uint32_t)__cvta_generic_to_shared(vb);
        #pragma unroll
        for (int ks = 0; ks < 4; ks++) {     // 4 k-steps of 16
            int kk = ks * 16;
            uint32_t af[2][4];
            #pragma unroll
            for (int mt = 0; mt < 2; mt++) {
                int r = wm * 32 + mt * 16;
                uint32_t a = pbase + (uint32_t)(((r + aRow) * PSTRH + kk + aColOff) * 2);
                ldm_x4(af[mt][0], af[mt][1], af[mt][2], af[mt][3], a);
            }
            #pragma unroll
            for (int ng = 0; ng < 4; ng++) { // 4 n-groups of 16
                int c0 = wn * 64 + ng * 16;
                uint32_t a = vbase + (uint32_t)(((kk + bRow) * VSTRH + c0 + bColOff) * 2);
                uint32_t b0, b1, b2, b3;
                ldm_x4_t(b0, b1, b2, b3, a);
                #pragma unroll
                for (int mt = 0; mt < 2; mt++) {
                    asm volatile(
                        "mma.sync.aligned.m16n8k16.row.col.f32.f16.f16.f32 "
                        "{%0,%1,%2,%3}, {%4,%5,%6,%7}, {%8,%9}, {%0,%1,%2,%3};"
                        : "+f"(acc[mt][2*ng][0]), "+f"(acc[mt][2*ng][1]),
                          "+f"(acc[mt][2*ng][2]), "+f"(acc[mt][2*ng][3])
                        : "r"(af[mt][0]), "r"(af[mt][1]), "r"(af[mt][2]), "r"(af[mt][3]),
                          "r"(b0), "r"(b1));
                    asm volatile(
                        "mma.sync.aligned.m16n8k16.row.col.f32.f16.f16.f32 "
                        "{%0,%1,%2,%3}, {%4,%5,%6,%7}, {%8,%9}, {%0,%1,%2,%3};"
                        : "+f"(acc[mt][2*ng+1][0]), "+f"(acc[mt][2*ng+1][1]),
                          "+f"(acc[mt][2*ng+1][2]), "+f"(acc[mt][2*ng+1][3])
                        : "r"(af[mt][0]), "r"(af[mt][1]), "r"(af[mt][2]), "r"(af[mt][3]),
                          "r"(b2), "r"(b3));
                }
            }
        }
        __syncthreads();
    }
    // epilogue: divide by den, store
    const float* den = g_den + bh * SEQ + q0;
    #pragma unroll
    for (int mt = 0; mt < 2; mt++) {
        int r = wm * 32 + mt * 16 + g;
        float rd0 = 1.0f / den[r];
        float rd8 = 1.0f / den[r + 8];
        #pragma unroll
        for (int nt = 0; nt < 8; nt++) {
            int col = h * HD + wn * 64 + nt * 8 + 2 * tig;
            size_t row = (size_t)(b * SEQ + q0 + r);
            *(float2*)(g_ho + row * DIM + col) =
                make_float2(acc[mt][nt][0] * rd0, acc[mt][nt][1] * rd0);
            *(float2*)(g_ho + (row + 8) * DIM + col) =
                make_float2(acc[mt][nt][2] * rd8, acc[mt][nt][3] * rd8);
        }
    }
}

// ---------------------------------------------------------------------------
extern "C" void kernel_launch(void* const* d_in, const int* in_sizes, int n_in,
                              void* d_out, int out_size) {
    const float* x      = (const float*)d_in[0];
    const float* mass_w = (const float*)d_in[1];
    const float* v_w    = (const float*)d_in[2];
    const float* out_w  = (const float*)d_in[3];
    const float* pos    = (const float*)d_in[4];
    float* out = (float*)d_out;

    void *pvh = nullptr, *pho = nullptr;
    cudaGetSymbolAddress(&pvh, g_vh);
    cudaGetSymbolAddress(&pho, g_ho);
    cudaFuncSetAttribute(attn_gemm,
                         cudaFuncAttributeMaxDynamicSharedMemorySize, ATTN2_SMEM_BYTES);

    dist_kernel<<<(SEQ * SEQ) / 256, 256>>>(pos);
    masses_kernel<<<(BATCH * SEQ * HEADS * 32) / 256, 256>>>(x, mass_w);
    gemm_tf32<true><<<dim3(DIM / 128, M_ROWS / 128), 256>>>(x, v_w, pvh);
    pgen_kernel<<<dim3(SEQ / 64, BH), 256>>>();
    attn_gemm<<<dim3(SEQ / 128, BH), 256, ATTN2_SMEM_BYTES>>>();
    gemm_tf32<false><<<dim3(DIM / 128, M_ROWS / 128), 256>>>((const float*)pho, out_w, out);
}

// round 11
// speedup vs baseline: 3.4186x; 1.0050x over previous
#include <cuda_runtime.h>
#include <cuda_fp16.h>
#include <math.h>
#include <stdint.h>

constexpr int BATCH = 2;
constexpr int SEQ   = 2048;
constexpr int DIM   = 1024;
constexpr int HEADS = 8;
constexpr int HD    = 128;
constexpr int M_ROWS = BATCH * SEQ;  // 4096
constexpr int BH    = BATCH * HEADS; // 16

__device__ float  g_rinv[SEQ * SEQ];                 // 16 MB
__device__ float  g_masses[BH * SEQ];
__device__ __half g_vh[M_ROWS * DIM];                // 8 MB (fp16 V)
__device__ float  g_ho[M_ROWS * DIM];                // 16 MB
__device__ __half g_p[(size_t)BH * SEQ * SEQ];       // 128 MB (fp16 P)
__device__ float  g_den[BH * SEQ];

__device__ __forceinline__ uint32_t f2tf32(float x) {
    uint32_t u;
    asm("cvt.rna.tf32.f32 %0, %1;" : "=r"(u) : "f"(x));
    return u;
}

// ---------------------------------------------------------------------------
// Kernel 1: rinv
// ---------------------------------------------------------------------------
__global__ __launch_bounds__(256) void dist_kernel(const float* __restrict__ pe) {
    int idx = blockIdx.x * 256 + threadIdx.x;
    int q = idx >> 11;
    int k = idx & (SEQ - 1);
    const float4* P = (const float4*)pe;
    float4 qa = P[q * 2], qb = P[q * 2 + 1];
    float4 ka = P[k * 2], kb = P[k * 2 + 1];
    float dx0 = qa.x - ka.x, dx1 = qa.y - ka.y, dx2 = qa.z - ka.z, dx3 = qa.w - ka.w;
    float dx4 = qb.x - kb.x, dx5 = qb.y - kb.y, dx6 = qb.z - kb.z, dx7 = qb.w - kb.w;
    float ss = dx0*dx0 + dx1*dx1 + dx2*dx2 + dx3*dx3
             + dx4*dx4 + dx5*dx5 + dx6*dx6 + dx7*dx7;
    float d = sqrtf(ss + 1e-12f);
    d = d * (1.0f + 0.15f * sinf(d));
    d = fmaxf(d, 0.0f);
    g_rinv[idx] = 1.0f / (d * d + 1e-6f);
}

// ---------------------------------------------------------------------------
// Kernel 2: masses
// ---------------------------------------------------------------------------
__global__ __launch_bounds__(256) void masses_kernel(const float* __restrict__ x,
                                                     const float* __restrict__ mw) {
    int warp = (blockIdx.x * 256 + threadIdx.x) >> 5;
    int lane = threadIdx.x & 31;
    int h  = warp & (HEADS - 1);
    int bs = warp >> 3;
    const float4* xp = (const float4*)(x + (size_t)bs * DIM + h * HD);
    const float4* wp = (const float4*)(mw + h * HD);
    float4 xv = xp[lane];
    float4 wv = wp[lane];
    float s = xv.x*wv.x + xv.y*wv.y + xv.z*wv.z + xv.w*wv.w;
    #pragma unroll
    for (int o = 16; o; o >>= 1) s += __shfl_xor_sync(0xFFFFFFFFu, s, o);
    if (lane == 0) {
        int b = bs >> 11, ss = bs & (SEQ - 1);
        g_masses[(b * HEADS + h) * SEQ + ss] = 1.0f / (1.0f + __expf(-s));
    }
}

// ---------------------------------------------------------------------------
// Kernels 3/5: tf32 tensor-core GEMM (double-buffered). HALF_OUT selects
// fp16 epilogue (V gemm) vs fp32 (out gemm).
// ---------------------------------------------------------------------------
constexpr int GBK = 16;

__device__ __forceinline__ void gemm_fill(uint32_t (*Asb)[GBK + 4],
                                          uint32_t (*Wsb)[GBK + 4],
                                          const float* __restrict__ A,
                                          const float* __restrict__ W,
                                          int bm, int bn, int k0, int t) {
    #pragma unroll
    for (int i = 0; i < 2; i++) {
        int idx = t + i * 256;
        int row = idx >> 2, seg = (idx & 3) * 4;
        float4 a = *(const float4*)(A + (size_t)(bm + row) * DIM + k0 + seg);
        float4 w = *(const float4*)(W + (size_t)(bn + row) * DIM + k0 + seg);
        Asb[row][seg + 0] = f2tf32(a.x); Asb[row][seg + 1] = f2tf32(a.y);
        Asb[row][seg + 2] = f2tf32(a.z); Asb[row][seg + 3] = f2tf32(a.w);
        Wsb[row][seg + 0] = f2tf32(w.x); Wsb[row][seg + 1] = f2tf32(w.y);
        Wsb[row][seg + 2] = f2tf32(w.z); Wsb[row][seg + 3] = f2tf32(w.w);
    }
}

template <bool HALF_OUT>
__global__ __launch_bounds__(256) void gemm_tf32(const float* __restrict__ A,
                                                 const float* __restrict__ W,
                                                 void* __restrict__ Cv) {
    __shared__ uint32_t As[2][128][GBK + 4];
    __shared__ uint32_t Ws[2][128][GBK + 4];
    const int t    = threadIdx.x;
    const int warp = t >> 5, lane = t & 31;
    const int wm = warp >> 1, wn = warp & 1;
    const int g  = lane >> 2, tig = lane & 3;
    const int bm = blockIdx.y * 128, bn = blockIdx.x * 128;

    float acc[2][8][4];
    #pragma unroll
    for (int mt = 0; mt < 2; mt++)
        #pragma unroll
        for (int nt = 0; nt < 8; nt++)
            #pragma unroll
            for (int c = 0; c < 4; c++) acc[mt][nt][c] = 0.0f;

    gemm_fill(As[0], Ws[0], A, W, bm, bn, 0, t);

    constexpr int NIT = DIM / GBK;
    for (int i = 0; i < NIT; i++) {
        __syncthreads();
        if (i + 1 < NIT)
            gemm_fill(As[(i + 1) & 1], Ws[(i + 1) & 1], A, W, bm, bn, (i + 1) * GBK, t);
        uint32_t (*Ab)[GBK + 4] = As[i & 1];
        uint32_t (*Wb)[GBK + 4] = Ws[i & 1];
        #pragma unroll
        for (int kk = 0; kk < GBK; kk += 8) {
            uint32_t af[2][4];
            #pragma unroll
            for (int mt = 0; mt < 2; mt++) {
                int r = wm * 32 + mt * 16;
                af[mt][0] = Ab[r + g][kk + tig];
                af[mt][1] = Ab[r + g + 8][kk + tig];
                af[mt][2] = Ab[r + g][kk + tig + 4];
                af[mt][3] = Ab[r + g + 8][kk + tig + 4];
            }
            uint32_t bf[8][2];
            #pragma unroll
            for (int nt = 0; nt < 8; nt++) {
                int c = wn * 64 + nt * 8;
                bf[nt][0] = Wb[c + g][kk + tig];
                bf[nt][1] = Wb[c + g][kk + tig + 4];
            }
            #pragma unroll
            for (int mt = 0; mt < 2; mt++)
                #pragma unroll
                for (int nt = 0; nt < 8; nt++) {
                    asm volatile(
                        "mma.sync.aligned.m16n8k8.row.col.f32.tf32.tf32.f32 "
                        "{%0,%1,%2,%3}, {%4,%5,%6,%7}, {%8,%9}, {%0,%1,%2,%3};"
                        : "+f"(acc[mt][nt][0]), "+f"(acc[mt][nt][1]),
                          "+f"(acc[mt][nt][2]), "+f"(acc[mt][nt][3])
                        : "r"(af[mt][0]), "r"(af[mt][1]), "r"(af[mt][2]), "r"(af[mt][3]),
                          "r"(bf[nt][0]), "r"(bf[nt][1]));
                }
        }
    }
    #pragma unroll
    for (int mt = 0; mt < 2; mt++) {
        #pragma unroll
        for (int nt = 0; nt < 8; nt++) {
            size_t r0 = (size_t)(bm + wm * 32 + mt * 16 + g);
            int col = bn + wn * 64 + nt * 8 + 2 * tig;
            if (HALF_OUT) {
                __half* C = (__half*)Cv;
                *(__half2*)(C + r0 * DIM + col) =
                    __floats2half2_rn(acc[mt][nt][0], acc[mt][nt][1]);
                *(__half2*)(C + (r0 + 8) * DIM + col) =
                    __floats2half2_rn(acc[mt][nt][2], acc[mt][nt][3]);
            } else {
                float* C = (float*)Cv;
                *(float2*)(C + r0 * DIM + col) =
                    make_float2(acc[mt][nt][0], acc[mt][nt][1]);
                *(float2*)(C + (r0 + 8) * DIM + col) =
                    make_float2(acc[mt][nt][2], acc[mt][nt][3]);
            }
        }
    }
}

// ---------------------------------------------------------------------------
// Kernel 4a: pgen — P[bh][q][k] = fp16(exp(min(mq*mk*rinv,50)-50)),
// den[bh][q] = fp32 row sum (from unrounded values).
// Grid (SEQ/64, BH), 256 threads: thread = (qi = t>>2, part = t&3).
// ---------------------------------------------------------------------------
__global__ __launch_bounds__(256) void pgen_kernel() {
    const int bh = blockIdx.y;
    const int q0 = blockIdx.x * 64;
    const int t  = threadIdx.x;
    const int qi = q0 + (t >> 2), part = t & 3;
    const int k0p = part * 16;

    const float* mrow = g_masses + bh * SEQ;
    const float  mq   = mrow[qi];
    const float* rrow = g_rinv + (size_t)qi * SEQ;
    __half* prow = g_p + ((size_t)bh * SEQ + qi) * SEQ;

    float denr = 0.0f;
    for (int kb = 0; kb < SEQ; kb += 64) {
        const float* rp = rrow + kb + k0p;
        const float* mk = mrow + kb + k0p;
        #pragma unroll
        for (int j4 = 0; j4 < 4; j4++) {
            float4 rv = *(const float4*)(rp + j4 * 4);
            float4 mv = *(const float4*)(mk + j4 * 4);
            float e0 = __expf(fminf(mq * mv.x * rv.x, 50.0f) - 50.0f);
            float e1 = __expf(fminf(mq * mv.y * rv.y, 50.0f) - 50.0f);
            float e2 = __expf(fminf(mq * mv.z * rv.z, 50.0f) - 50.0f);
            float e3 = __expf(fminf(mq * mv.w * rv.w, 50.0f) - 50.0f);
            denr += (e0 + e1) + (e2 + e3);
            __half2 h01 = __floats2half2_rn(e0, e1);
            __half2 h23 = __floats2half2_rn(e2, e3);
            *(uint2*)(prow + kb + k0p + j4 * 4) =
                make_uint2(*(uint32_t*)&h01, *(uint32_t*)&h23);
        }
    }
    denr += __shfl_xor_sync(0xFFFFFFFFu, denr, 1);
    denr += __shfl_xor_sync(0xFFFFFFFFu, denr, 2);
    if (part == 0) g_den[bh * SEQ + qi] = denr;
}

// ---------------------------------------------------------------------------
// Kernel 4b: attn_gemm — head_out = (P @ V_h) / den, fp16 m16n8k16.
// Tile: 128 q x 128 hd, K chunks of 64. 8 warps (4m x 2n), warp 32x64.
// P via ldmatrix.x4, V via ldmatrix.x4.trans (V stays [k][c] layout).
// cp.async double-buffered.
// ---------------------------------------------------------------------------
constexpr int KCH   = 64;
constexpr int PSTRH = 72;    // halfs per P row (64+8): 144B ≡ 4 words mod 32
constexpr int VSTRH = 136;   // halfs per V row (128+8): 272B ≡ 4 words mod 32
constexpr int PBUF  = 128 * PSTRH;   // 9216 halfs
constexpr int VBUF  = KCH * VSTRH;   // 8704 halfs
constexpr int ATTN2_SMEM_BYTES = 2 * (PBUF + VBUF) * 2;  // 71680

__device__ __forceinline__ void ldm_x4(uint32_t& r0, uint32_t& r1,
                                       uint32_t& r2, uint32_t& r3, uint32_t a) {
    asm volatile("ldmatrix.sync.aligned.m8n8.x4.shared.b16 {%0,%1,%2,%3}, [%4];"
                 : "=r"(r0), "=r"(r1), "=r"(r2), "=r"(r3) : "r"(a));
}
__device__ __forceinline__ void ldm_x4_t(uint32_t& r0, uint32_t& r1,
                                         uint32_t& r2, uint32_t& r3, uint32_t a) {
    asm volatile("ldmatrix.sync.aligned.m8n8.x4.trans.shared.b16 {%0,%1,%2,%3}, [%4];"
                 : "=r"(r0), "=r"(r1), "=r"(r2), "=r"(r3) : "r"(a));
}

__device__ __forceinline__ void attn2_stage(__half* pb, __half* vb,
                                            int bh, int b, int h,
                                            int q0, int kb, int t) {
    uint32_t pdst = (uint32_t)__cvta_generic_to_shared(pb);
    uint32_t vdst = (uint32_t)__cvta_generic_to_shared(vb);
    #pragma unroll
    for (int i = 0; i < 4; i++) {           // P tile: 128 rows x 64 halfs
        int e = t + i * 256;
        int row = e >> 3, seg = e & 7;
        const __half* src = g_p + ((size_t)bh * SEQ + q0 + row) * SEQ + kb + seg * 8;
        asm volatile("cp.async.ca.shared.global [%0], [%1], 16;\n"
                     :: "r"(pdst + (uint32_t)((row * PSTRH + seg * 8) * 2)), "l"(src));
    }
    #pragma unroll
    for (int i = 0; i < 4; i++) {           // V tile: 64 rows x 128 halfs
        int e = t + i * 256;
        int row = e >> 4, seg = e & 15;
        const __half* src = g_vh + ((size_t)(b * SEQ + kb + row)) * DIM + h * HD + seg * 8;
        asm volatile("cp.async.ca.shared.global [%0], [%1], 16;\n"
                     :: "r"(vdst + (uint32_t)((row * VSTRH + seg * 8) * 2)), "l"(src));
    }
    asm volatile("cp.async.commit_group;\n" ::: "memory");
}

__global__ __launch_bounds__(256) void attn_gemm() {
    extern __shared__ __half smh[];
    const int bh = blockIdx.y;
    const int b  = bh >> 3;
    const int h  = bh & (HEADS - 1);
    const int q0 = blockIdx.x * 128;
    const int t  = threadIdx.x;
    const int warp = t >> 5, lane = t & 31;
    const int g = lane >> 2, tig = lane & 3;
    const int wm = warp >> 1, wn = warp & 1;     // 4m x 2n

    float acc[2][8][4];
    #pragma unroll
    for (int mt = 0; mt < 2; mt++)
        #pragma unroll
        for (int nt = 0; nt < 8; nt++)
            #pragma unroll
            for (int c = 0; c < 4; c++) acc[mt][nt][c] = 0.0f;

    // ldmatrix lane address components
    const int aRow = lane & 15, aColOff = (lane >> 4) << 3;            // A
    const int bRow = (lane & 7) + (((lane >> 3) & 1) << 3);            // B (trans)
    const int bColOff = (lane >> 4) << 3;

    attn2_stage(smh, smh + PBUF, bh, b, h, q0, 0, t);

    constexpr int NCH = SEQ / KCH;   // 32
    for (int i = 0; i < NCH; i++) {
        if (i + 1 < NCH) {
            __half* nb = smh + ((i + 1) & 1) * (PBUF + VBUF);
            attn2_stage(nb, nb + PBUF, bh, b, h, q0, (i + 1) * KCH, t);
            asm volatile("cp.async.wait_group 1;\n" ::: "memory");
        } else {
            asm volatile("cp.async.wait_group 0;\n" ::: "memory");
        }
        __syncthreads();
        const __half* pb = smh + (i & 1) * (PBUF + VBUF);
        const __half* vb = pb + PBUF;
        uint32_t pbase = (uint32_t)__cvta_generic_to_shared(pb);
        uint32_t vbase = (uint32_t)__cvta_generic_to_shared(vb);
        #pragma unroll
        for (int ks = 0; ks < 4; ks++) {     // 4 k-steps of 16
            int kk = ks * 16;
            uint32_t af[2][4];
            #pragma unroll
            for (int mt = 0; mt < 2; mt++) {
                int r = wm * 32 + mt * 16;
                uint32_t a = pbase + (uint32_t)(((r + aRow) * PSTRH + kk + aColOff) * 2);
                ldm_x4(af[mt][0], af[mt][1], af[mt][2], af[mt][3], a);
            }
            #pragma unroll
            for (int ng = 0; ng < 4; ng++) { // 4 n-groups of 16
                int c0 = wn * 64 + ng * 16;
                uint32_t a = vbase + (uint32_t)(((kk + bRow) * VSTRH + c0 + bColOff) * 2);
                uint32_t b0, b1, b2, b3;
                ldm_x4_t(b0, b1, b2, b3, a);
                #pragma unroll
                for (int mt = 0; mt < 2; mt++) {
                    asm volatile(
                        "mma.sync.aligned.m16n8k16.row.col.f32.f16.f16.f32 "
                        "{%0,%1,%2,%3}, {%4,%5,%6,%7}, {%8,%9}, {%0,%1,%2,%3};"
                        : "+f"(acc[mt][2*ng][0]), "+f"(acc[mt][2*ng][1]),
                          "+f"(acc[mt][2*ng][2]), "+f"(acc[mt][2*ng][3])
                        : "r"(af[mt][0]), "r"(af[mt][1]), "r"(af[mt][2]), "r"(af[mt][3]),
                          "r"(b0), "r"(b1));
                    asm volatile(
                        "mma.sync.aligned.m16n8k16.row.col.f32.f16.f16.f32 "
                        "{%0,%1,%2,%3}, {%4,%5,%6,%7}, {%8,%9}, {%0,%1,%2,%3};"
                        : "+f"(acc[mt][2*ng+1][0]), "+f"(acc[mt][2*ng+1][1]),
                          "+f"(acc[mt][2*ng+1][2]), "+f"(acc[mt][2*ng+1][3])
                        : "r"(af[mt][0]), "r"(af[mt][1]), "r"(af[mt][2]), "r"(af[mt][3]),
                          "r"(b2), "r"(b3));
                }
            }
        }
        __syncthreads();
    }
    // epilogue: divide by den, store
    const float* den = g_den + bh * SEQ + q0;
    #pragma unroll
    for (int mt = 0; mt < 2; mt++) {
        int r = wm * 32 + mt * 16 + g;
        float rd0 = 1.0f / den[r];
        float rd8 = 1.0f / den[r + 8];
        #pragma unroll
        for (int nt = 0; nt < 8; nt++) {
            int col = h * HD + wn * 64 + nt * 8 + 2 * tig;
            size_t row = (size_t)(b * SEQ + q0 + r);
            *(float2*)(g_ho + row * DIM + col) =
                make_float2(acc[mt][nt][0] * rd0, acc[mt][nt][1] * rd0);
            *(float2*)(g_ho + (row + 8) * DIM + col) =
                make_float2(acc[mt][nt][2] * rd8, acc[mt][nt][3] * rd8);
        }
    }
}

// ---------------------------------------------------------------------------
extern "C" void kernel_launch(void* const* d_in, const int* in_sizes, int n_in,
                              void* d_out, int out_size) {
    const float* x      = (const float*)d_in[0];
    const float* mass_w = (const float*)d_in[1];
    const float* v_w    = (const float*)d_in[2];
    const float* out_w  = (const float*)d_in[3];
    const float* pos    = (const float*)d_in[4];
    float* out = (float*)d_out;

    void *pvh = nullptr, *pho = nullptr;
    cudaGetSymbolAddress(&pvh, g_vh);
    cudaGetSymbolAddress(&pho, g_ho);
    cudaFuncSetAttribute(attn_gemm,
                         cudaFuncAttributeMaxDynamicSharedMemorySize, ATTN2_SMEM_BYTES);

    dist_kernel<<<(SEQ * SEQ) / 256, 256>>>(pos);
    masses_kernel<<<(BATCH * SEQ * HEADS * 32) / 256, 256>>>(x, mass_w);
    gemm_tf32<true><<<dim3(DIM / 128, M_ROWS / 128), 256>>>(x, v_w, pvh);
    pgen_kernel<<<dim3(SEQ / 64, BH), 256>>>();
    attn_gemm<<<dim3(SEQ / 128, BH), 256, ATTN2_SMEM_BYTES>>>();
    gemm_tf32<false><<<dim3(DIM / 128, M_ROWS / 128), 256>>>((const float*)pho, out_w, out);
}

// round 12
// speedup vs baseline: 4.9442x; 1.4463x over previous
#include <cuda_runtime.h>
#include <cuda_fp16.h>
#include <math.h>
#include <stdint.h>

constexpr int BATCH = 2;
constexpr int SEQ   = 2048;
constexpr int DIM   = 1024;
constexpr int HEADS = 8;
constexpr int HD    = 128;
constexpr int M_ROWS = BATCH * SEQ;  // 4096
constexpr int BH    = BATCH * HEADS; // 16
constexpr float BOUND_SKIP = 30.0f;  // skip chunk if max force < 30 (p < e^-20)

__device__ float  g_rinv[SEQ * SEQ];                 // 16 MB
__device__ float  g_masses[BH * SEQ];
__device__ __half g_vh[M_ROWS * DIM];                // 8 MB (fp16 V)
__device__ float  g_ho[M_ROWS * DIM];                // 16 MB
__device__ __half g_p[(size_t)BH * SEQ * SEQ];       // sparse fp16 P
__device__ float  g_den[BH * SEQ];
__device__ float  g_rmax[16][32];                    // [qt128][kt64] tile max of rinv
__device__ float  g_mmax[BH][32];                    // per-64-chunk mass max
__device__ uint32_t g_mask[BH][16];                  // surviving-chunk bitmask per qt128

__device__ __forceinline__ uint32_t f2tf32(float x) {
    uint32_t u;
    asm("cvt.rna.tf32.f32 %0, %1;" : "=r"(u) : "f"(x));
    return u;
}
__device__ __forceinline__ void atomicMaxF(float* a, float v) {
    atomicMax((int*)a, __float_as_int(v));   // valid: all values >= 0
}

// ---------------------------------------------------------------------------
// Kernel 0: zero the rmax accumulators
// ---------------------------------------------------------------------------
__global__ void zero_rmax() {
    ((float*)g_rmax)[threadIdx.x] = 0.0f;    // 512 threads
}

// ---------------------------------------------------------------------------
// Kernel 1: rinv + fused per-tile (128q x 64k) max via atomicMax
// ---------------------------------------------------------------------------
__global__ __launch_bounds__(256) void dist_kernel(const float* __restrict__ pe) {
    __shared__ float wmax[8];
    int idx = blockIdx.x * 256 + threadIdx.x;
    int q = idx >> 11;
    int k = idx & (SEQ - 1);
    const float4* P = (const float4*)pe;
    float4 qa = P[q * 2], qb = P[q * 2 + 1];
    float4 ka = P[k * 2], kb = P[k * 2 + 1];
    float dx0 = qa.x - ka.x, dx1 = qa.y - ka.y, dx2 = qa.z - ka.z, dx3 = qa.w - ka.w;
    float dx4 = qb.x - kb.x, dx5 = qb.y - kb.y, dx6 = qb.z - kb.z, dx7 = qb.w - kb.w;
    float ss = dx0*dx0 + dx1*dx1 + dx2*dx2 + dx3*dx3
             + dx4*dx4 + dx5*dx5 + dx6*dx6 + dx7*dx7;
    float d = sqrtf(ss + 1e-12f);
    d = d * (1.0f + 0.15f * __sinf(d));
    d = fmaxf(d, 0.0f);
    float r = 1.0f / (d * d + 1e-6f);
    g_rinv[idx] = r;
    // tile max: block covers one q row, 256 consecutive k (4 segments of 64)
    float m = r;
    #pragma unroll
    for (int o = 16; o; o >>= 1) m = fmaxf(m, __shfl_xor_sync(0xFFFFFFFFu, m, o));
    if ((threadIdx.x & 31) == 0) wmax[threadIdx.x >> 5] = m;
    __syncthreads();
    if (threadIdx.x < 4) {
        float sm = fmaxf(wmax[2 * threadIdx.x], wmax[2 * threadIdx.x + 1]);
        int kbase = (blockIdx.x * 256) & (SEQ - 1);
        atomicMaxF(&g_rmax[q >> 7][(kbase >> 6) + threadIdx.x], sm);
    }
}

// ---------------------------------------------------------------------------
// Kernel 2: masses
// ---------------------------------------------------------------------------
__global__ __launch_bounds__(256) void masses_kernel(const float* __restrict__ x,
                                                     const float* __restrict__ mw) {
    int warp = (blockIdx.x * 256 + threadIdx.x) >> 5;
    int lane = threadIdx.x & 31;
    int h  = warp & (HEADS - 1);
    int bs = warp >> 3;
    const float4* xp = (const float4*)(x + (size_t)bs * DIM + h * HD);
    const float4* wp = (const float4*)(mw + h * HD);
    float4 xv = xp[lane];
    float4 wv = wp[lane];
    float s = xv.x*wv.x + xv.y*wv.y + xv.z*wv.z + xv.w*wv.w;
    #pragma unroll
    for (int o = 16; o; o >>= 1) s += __shfl_xor_sync(0xFFFFFFFFu, s, o);
    if (lane == 0) {
        int b = bs >> 11, ss = bs & (SEQ - 1);
        g_masses[(b * HEADS + h) * SEQ + ss] = 1.0f / (1.0f + __expf(-s));
    }
}

// ---------------------------------------------------------------------------
// Kernel 2b: prep — mass chunk maxima + survivor masks (1 block, 512 thr)
// ---------------------------------------------------------------------------
__global__ void prep_kernel() {
    int tid = threadIdx.x;
    {   // phase 1: mmax[bh][kt] over 64 masses
        int bh = tid >> 5, kt = tid & 31;
        float m = 0.0f;
        const float* p = g_masses + bh * SEQ + kt * 64;
        #pragma unroll 8
        for (int j = 0; j < 64; j++) m = fmaxf(m, p[j]);
        g_mmax[bh][kt] = m;
    }
    __syncthreads();
    if (tid < 256) {  // phase 2: masks per (bh, qt128)
        int bh = tid >> 4, qt = tid & 15;
        float mq = fmaxf(g_mmax[bh][2 * qt], g_mmax[bh][2 * qt + 1]);
        uint32_t msk = 0;
        #pragma unroll
        for (int kt = 0; kt < 32; kt++) {
            float bound = mq * g_mmax[bh][kt] * g_rmax[qt][kt];
            if (bound > BOUND_SKIP) msk |= (1u << kt);
        }
        g_mask[bh][qt] = msk;
    }
}

// ---------------------------------------------------------------------------
// Kernels 3/5: tf32 tensor-core GEMM (double-buffered), HALF_OUT epilogue
// ---------------------------------------------------------------------------
constexpr int GBK = 16;

__device__ __forceinline__ void gemm_fill(uint32_t (*Asb)[GBK + 4],
                                          uint32_t (*Wsb)[GBK + 4],
                                          const float* __restrict__ A,
                                          const float* __restrict__ W,
                                          int bm, int bn, int k0, int t) {
    #pragma unroll
    for (int i = 0; i < 2; i++) {
        int idx = t + i * 256;
        int row = idx >> 2, seg = (idx & 3) * 4;
        float4 a = *(const float4*)(A + (size_t)(bm + row) * DIM + k0 + seg);
        float4 w = *(const float4*)(W + (size_t)(bn + row) * DIM + k0 + seg);
        Asb[row][seg + 0] = f2tf32(a.x); Asb[row][seg + 1] = f2tf32(a.y);
        Asb[row][seg + 2] = f2tf32(a.z); Asb[row][seg + 3] = f2tf32(a.w);
        Wsb[row][seg + 0] = f2tf32(w.x); Wsb[row][seg + 1] = f2tf32(w.y);
        Wsb[row][seg + 2] = f2tf32(w.z); Wsb[row][seg + 3] = f2tf32(w.w);
    }
}

template <bool HALF_OUT>
__global__ __launch_bounds__(256) void gemm_tf32(const float* __restrict__ A,
                                                 const float* __restrict__ W,
                                                 void* __restrict__ Cv) {
    __shared__ uint32_t As[2][128][GBK + 4];
    __shared__ uint32_t Ws[2][128][GBK + 4];
    const int t    = threadIdx.x;
    const int warp = t >> 5, lane = t & 31;
    const int wm = warp >> 1, wn = warp & 1;
    const int g  = lane >> 2, tig = lane & 3;
    const int bm = blockIdx.y * 128, bn = blockIdx.x * 128;

    float acc[2][8][4];
    #pragma unroll
    for (int mt = 0; mt < 2; mt++)
        #pragma unroll
        for (int nt = 0; nt < 8; nt++)
            #pragma unroll
            for (int c = 0; c < 4; c++) acc[mt][nt][c] = 0.0f;

    gemm_fill(As[0], Ws[0], A, W, bm, bn, 0, t);

    constexpr int NIT = DIM / GBK;
    for (int i = 0; i < NIT; i++) {
        __syncthreads();
        if (i + 1 < NIT)
            gemm_fill(As[(i + 1) & 1], Ws[(i + 1) & 1], A, W, bm, bn, (i + 1) * GBK, t);
        uint32_t (*Ab)[GBK + 4] = As[i & 1];
        uint32_t (*Wb)[GBK + 4] = Ws[i & 1];
        #pragma unroll
        for (int kk = 0; kk < GBK; kk += 8) {
            uint32_t af[2][4];
            #pragma unroll
            for (int mt = 0; mt < 2; mt++) {
                int r = wm * 32 + mt * 16;
                af[mt][0] = Ab[r + g][kk + tig];
                af[mt][1] = Ab[r + g + 8][kk + tig];
                af[mt][2] = Ab[r + g][kk + tig + 4];
                af[mt][3] = Ab[r + g + 8][kk + tig + 4];
            }
            uint32_t bf[8][2];
            #pragma unroll
            for (int nt = 0; nt < 8; nt++) {
                int c = wn * 64 + nt * 8;
                bf[nt][0] = Wb[c + g][kk + tig];
                bf[nt][1] = Wb[c + g][kk + tig + 4];
            }
            #pragma unroll
            for (int mt = 0; mt < 2; mt++)
                #pragma unroll
                for (int nt = 0; nt < 8; nt++) {
                    asm volatile(
                        "mma.sync.aligned.m16n8k8.row.col.f32.tf32.tf32.f32 "
                        "{%0,%1,%2,%3}, {%4,%5,%6,%7}, {%8,%9}, {%0,%1,%2,%3};"
                        : "+f"(acc[mt][nt][0]), "+f"(acc[mt][nt][1]),
                          "+f"(acc[mt][nt][2]), "+f"(acc[mt][nt][3])
                        : "r"(af[mt][0]), "r"(af[mt][1]), "r"(af[mt][2]), "r"(af[mt][3]),
                          "r"(bf[nt][0]), "r"(bf[nt][1]));
                }
        }
    }
    #pragma unroll
    for (int mt = 0; mt < 2; mt++) {
        #pragma unroll
        for (int nt = 0; nt < 8; nt++) {
            size_t r0 = (size_t)(bm + wm * 32 + mt * 16 + g);
            int col = bn + wn * 64 + nt * 8 + 2 * tig;
            if (HALF_OUT) {
                __half* C = (__half*)Cv;
                *(__half2*)(C + r0 * DIM + col) =
                    __floats2half2_rn(acc[mt][nt][0], acc[mt][nt][1]);
                *(__half2*)(C + (r0 + 8) * DIM + col) =
                    __floats2half2_rn(acc[mt][nt][2], acc[mt][nt][3]);
            } else {
                float* C = (float*)Cv;
                *(float2*)(C + r0 * DIM + col) =
                    make_float2(acc[mt][nt][0], acc[mt][nt][1]);
                *(float2*)(C + (r0 + 8) * DIM + col) =
                    make_float2(acc[mt][nt][2], acc[mt][nt][3]);
            }
        }
    }
}

// ---------------------------------------------------------------------------
// Kernel 4a: pgen — only surviving chunks; fp16 P + fp32 den
// Grid (32 qt64, BH), 256 threads: thread = (qi, part of 16 k)
// ---------------------------------------------------------------------------
__global__ __launch_bounds__(256) void pgen_kernel() {
    const int bh = blockIdx.y;
    const int qt = blockIdx.x;                 // 64-row tile
    const uint32_t mask = g_mask[bh][qt >> 1];
    const int t  = threadIdx.x;
    const int qi = qt * 64 + (t >> 2), part = t & 3;
    const int k0p = part * 16;

    const float* mrow = g_masses + bh * SEQ;
    const float  mq   = mrow[qi];
    const float* rrow = g_rinv + (size_t)qi * SEQ;
    __half* prow = g_p + ((size_t)bh * SEQ + qi) * SEQ;

    float denr = 0.0f;
    uint32_t rem = mask;
    while (rem) {
        int kt = __ffs(rem) - 1; rem &= rem - 1;
        int kb = kt * 64;
        const float* rp = rrow + kb + k0p;
        const float* mk = mrow + kb + k0p;
        #pragma unroll
        for (int j4 = 0; j4 < 4; j4++) {
            float4 rv = *(const float4*)(rp + j4 * 4);
            float4 mv = *(const float4*)(mk + j4 * 4);
            float e0 = __expf(fminf(mq * mv.x * rv.x, 50.0f) - 50.0f);
            float e1 = __expf(fminf(mq * mv.y * rv.y, 50.0f) - 50.0f);
            float e2 = __expf(fminf(mq * mv.z * rv.z, 50.0f) - 50.0f);
            float e3 = __expf(fminf(mq * mv.w * rv.w, 50.0f) - 50.0f);
            denr += (e0 + e1) + (e2 + e3);
            __half2 h01 = __floats2half2_rn(e0, e1);
            __half2 h23 = __floats2half2_rn(e2, e3);
            *(uint2*)(prow + kb + k0p + j4 * 4) =
                make_uint2(*(uint32_t*)&h01, *(uint32_t*)&h23);
        }
    }
    denr += __shfl_xor_sync(0xFFFFFFFFu, denr, 1);
    denr += __shfl_xor_sync(0xFFFFFFFFu, denr, 2);
    if (part == 0) g_den[bh * SEQ + qi] = denr;
}

// ---------------------------------------------------------------------------
// Kernel 4b: attn_gemm — fp16 m16n8k16 over surviving chunks only
// ---------------------------------------------------------------------------
constexpr int KCH   = 64;
constexpr int PSTRH = 72;
constexpr int VSTRH = 136;
constexpr int PBUF  = 128 * PSTRH;
constexpr int VBUF  = KCH * VSTRH;
constexpr int ATTN2_SMEM_BYTES = 2 * (PBUF + VBUF) * 2;  // 71680

__device__ __forceinline__ void ldm_x4(uint32_t& r0, uint32_t& r1,
                                       uint32_t& r2, uint32_t& r3, uint32_t a) {
    asm volatile("ldmatrix.sync.aligned.m8n8.x4.shared.b16 {%0,%1,%2,%3}, [%4];"
                 : "=r"(r0), "=r"(r1), "=r"(r2), "=r"(r3) : "r"(a));
}
__device__ __forceinline__ void ldm_x4_t(uint32_t& r0, uint32_t& r1,
                                         uint32_t& r2, uint32_t& r3, uint32_t a) {
    asm volatile("ldmatrix.sync.aligned.m8n8.x4.trans.shared.b16 {%0,%1,%2,%3}, [%4];"
                 : "=r"(r0), "=r"(r1), "=r"(r2), "=r"(r3) : "r"(a));
}

__device__ __forceinline__ void attn2_stage(__half* pb, __half* vb,
                                            int bh, int b, int h,
                                            int q0, int kb, int t) {
    uint32_t pdst = (uint32_t)__cvta_generic_to_shared(pb);
    uint32_t vdst = (uint32_t)__cvta_generic_to_shared(vb);
    #pragma unroll
    for (int i = 0; i < 4; i++) {
        int e = t + i * 256;
        int row = e >> 3, seg = e & 7;
        const __half* src = g_p + ((size_t)bh * SEQ + q0 + row) * SEQ + kb + seg * 8;
        asm volatile("cp.async.ca.shared.global [%0], [%1], 16;\n"
                     :: "r"(pdst + (uint32_t)((row * PSTRH + seg * 8) * 2)), "l"(src));
    }
    #pragma unroll
    for (int i = 0; i < 4; i++) {
        int e = t + i * 256;
        int row = e >> 4, seg = e & 15;
        const __half* src = g_vh + ((size_t)(b * SEQ + kb + row)) * DIM + h * HD + seg * 8;
        asm volatile("cp.async.ca.shared.global [%0], [%1], 16;\n"
                     :: "r"(vdst + (uint32_t)((row * VSTRH + seg * 8) * 2)), "l"(src));
    }
    asm volatile("cp.async.commit_group;\n" ::: "memory");
}

__global__ __launch_bounds__(256) void attn_gemm() {
    extern __shared__ __half smh[];
    const int bh = blockIdx.y;
    const int b  = bh >> 3;
    const int h  = bh & (HEADS - 1);
    const int q0 = blockIdx.x * 128;
    const int t  = threadIdx.x;
    const int warp = t >> 5, lane = t & 31;
    const int g = lane >> 2, tig = lane & 3;
    const int wm = warp >> 1, wn = warp & 1;

    float acc[2][8][4];
    #pragma unroll
    for (int mt = 0; mt < 2; mt++)
        #pragma unroll
        for (int nt = 0; nt < 8; nt++)
            #pragma unroll
            for (int c = 0; c < 4; c++) acc[mt][nt][c] = 0.0f;

    const int aRow = lane & 15, aColOff = (lane >> 4) << 3;
    const int bRow = (lane & 7) + (((lane >> 3) & 1) << 3);
    const int bColOff = (lane >> 4) << 3;

    uint32_t rem = g_mask[bh][blockIdx.x];
    int cur = __ffs(rem) - 1; rem &= rem - 1;     // mask always nonzero (diag)
    attn2_stage(smh, smh + PBUF, bh, b, h, q0, cur * KCH, t);
    int ibuf = 0;

    while (cur >= 0) {
        int nxt = rem ? (int)__ffs(rem) - 1 : -1;
        if (nxt >= 0) {
            rem &= rem - 1;
            __half* nb = smh + (ibuf ^ 1) * (PBUF + VBUF);
            attn2_stage(nb, nb + PBUF, bh, b, h, q0, nxt * KCH, t);
            asm volatile("cp.async.wait_group 1;\n" ::: "memory");
        } else {
            asm volatile("cp.async.wait_group 0;\n" ::: "memory");
        }
        __syncthreads();
        const __half* pb = smh + ibuf * (PBUF + VBUF);
        const __half* vb = pb + PBUF;
        uint32_t pbase = (uint32_t)__cvta_generic_to_shared(pb);
        uint32_t vbase = (uint32_t)__cvta_generic_to_shared(vb);
        #pragma unroll
        for (int ks = 0; ks < 4; ks++) {
            int kk = ks * 16;
            uint32_t af[2][4];
            #pragma unroll
            for (int mt = 0; mt < 2; mt++) {
                int r = wm * 32 + mt * 16;
                uint32_t a = pbase + (uint32_t)(((r + aRow) * PSTRH + kk + aColOff) * 2);
                ldm_x4(af[mt][0], af[mt][1], af[mt][2], af[mt][3], a);
            }
            #pragma unroll
            for (int ng = 0; ng < 4; ng++) {
                int c0 = wn * 64 + ng * 16;
                uint32_t a = vbase + (uint32_t)(((kk + bRow) * VSTRH + c0 + bColOff) * 2);
                uint32_t b0, b1, b2, b3;
                ldm_x4_t(b0, b1, b2, b3, a);
                #pragma unroll
                for (int mt = 0; mt < 2; mt++) {
                    asm volatile(
                        "mma.sync.aligned.m16n8k16.row.col.f32.f16.f16.f32 "
                        "{%0,%1,%2,%3}, {%4,%5,%6,%7}, {%8,%9}, {%0,%1,%2,%3};"
                        : "+f"(acc[mt][2*ng][0]), "+f"(acc[mt][2*ng][1]),
                          "+f"(acc[mt][2*ng][2]), "+f"(acc[mt][2*ng][3])
                        : "r"(af[mt][0]), "r"(af[mt][1]), "r"(af[mt][2]), "r"(af[mt][3]),
                          "r"(b0), "r"(b1));
                    asm volatile(
                        "mma.sync.aligned.m16n8k16.row.col.f32.f16.f16.f32 "
                        "{%0,%1,%2,%3}, {%4,%5,%6,%7}, {%8,%9}, {%0,%1,%2,%3};"
                        : "+f"(acc[mt][2*ng+1][0]), "+f"(acc[mt][2*ng+1][1]),
                          "+f"(acc[mt][2*ng+1][2]), "+f"(acc[mt][2*ng+1][3])
                        : "r"(af[mt][0]), "r"(af[mt][1]), "r"(af[mt][2]), "r"(af[mt][3]),
                          "r"(b2), "r"(b3));
                }
            }
        }
        __syncthreads();
        cur = nxt; ibuf ^= 1;
    }
    const float* den = g_den + bh * SEQ + q0;
    #pragma unroll
    for (int mt = 0; mt < 2; mt++) {
        int r = wm * 32 + mt * 16 + g;
        float rd0 = 1.0f / den[r];
        float rd8 = 1.0f / den[r + 8];
        #pragma unroll
        for (int nt = 0; nt < 8; nt++) {
            int col = h * HD + wn * 64 + nt * 8 + 2 * tig;
            size_t row = (size_t)(b * SEQ + q0 + r);
            *(float2*)(g_ho + row * DIM + col) =
                make_float2(acc[mt][nt][0] * rd0, acc[mt][nt][1] * rd0);
            *(float2*)(g_ho + (row + 8) * DIM + col) =
                make_float2(acc[mt][nt][2] * rd8, acc[mt][nt][3] * rd8);
        }
    }
}

// ---------------------------------------------------------------------------
extern "C" void kernel_launch(void* const* d_in, const int* in_sizes, int n_in,
                              void* d_out, int out_size) {
    const float* x      = (const float*)d_in[0];
    const float* mass_w = (const float*)d_in[1];
    const float* v_w    = (const float*)d_in[2];
    const float* out_w  = (const float*)d_in[3];
    const float* pos    = (const float*)d_in[4];
    float* out = (float*)d_out;

    void *pvh = nullptr, *pho = nullptr;
    cudaGetSymbolAddress(&pvh, g_vh);
    cudaGetSymbolAddress(&pho, g_ho);
    cudaFuncSetAttribute(attn_gemm,
                         cudaFuncAttributeMaxDynamicSharedMemorySize, ATTN2_SMEM_BYTES);

    zero_rmax<<<1, 512>>>();
    dist_kernel<<<(SEQ * SEQ) / 256, 256>>>(pos);
    masses_kernel<<<(BATCH * SEQ * HEADS * 32) / 256, 256>>>(x, mass_w);
    prep_kernel<<<1, 512>>>();
    gemm_tf32<true><<<dim3(DIM / 128, M_ROWS / 128), 256>>>(x, v_w, pvh);
    pgen_kernel<<<dim3(32, BH), 256>>>();
    attn_gemm<<<dim3(SEQ / 128, BH), 256, ATTN2_SMEM_BYTES>>>();
    gemm_tf32<false><<<dim3(DIM / 128, M_ROWS / 128), 256>>>((const float*)pho, out_w, out);
}